// round 6
// baseline (speedup 1.0000x reference)
#include <cuda_runtime.h>
#include <cuda_bf16.h>
#include <cstdint>

#define NPTS 8192
#define DIM 128
#define SSTRIDE 144                   // fp8 tile row stride bytes (128 + 16 pad)
#define TILE_BYTES (128 * SSTRIDE)    // 18432

// ---------------- scratch (device globals; no allocations allowed) ----------
__device__ uint8_t g_src8[NPTS * DIM];
__device__ uint8_t g_pos8[NPTS * DIM];
__device__ float g_dot[NPTS];
__device__ float g_lse_partial[128];   // [matrix(2)][row-tile(64)]
__device__ int   g_idx_is64;

// ---------------- PTX helpers ------------------------------------------------
__device__ __forceinline__ uint32_t smem_u32(const void* p) {
    uint32_t a;
    asm("{ .reg .u64 t; cvta.to.shared.u64 t, %1; cvt.u32.u64 %0, t; }"
        : "=r"(a) : "l"(p));
    return a;
}

__device__ __forceinline__ float ex2_approx(float x) {
    float y;
    asm("ex2.approx.f32 %0, %1;" : "=f"(y) : "f"(x));
    return y;
}

#define CP_ASYNC16(dst, src) \
    asm volatile("cp.async.cg.shared.global [%0], [%1], 16;" :: "r"(dst), "l"(src) : "memory")
#define CP_COMMIT() asm volatile("cp.async.commit_group;" ::: "memory")
#define CP_WAIT1()  asm volatile("cp.async.wait_group 1;" ::: "memory")
#define CP_WAIT0()  asm volatile("cp.async.wait_group 0;" ::: "memory")

#define LDMATRIX_X4(r0, r1, r2, r3, addr) \
    asm volatile("ldmatrix.sync.aligned.m8n8.x4.shared.b16 {%0,%1,%2,%3}, [%4];" \
                 : "=r"(r0), "=r"(r1), "=r"(r2), "=r"(r3) : "r"(addr))
#define LDMATRIX_X2(r0, r1, addr) \
    asm volatile("ldmatrix.sync.aligned.m8n8.x2.shared.b16 {%0,%1}, [%2];" \
                 : "=r"(r0), "=r"(r1) : "r"(addr))

// FP8 e4m3 MMA: m16n8k32, f32 accumulate. Fragment layouts map 1:1 onto the
// b16 ldmatrix pattern used for bf16 m16n8k16 (fp8 pair == one b16 element).
#define MMA_FP8(c0, c1, c2, c3, a0, a1, a2, a3, b0, b1) \
    asm volatile("mma.sync.aligned.m16n8k32.row.col.f32.e4m3.e4m3.f32 " \
                 "{%0,%1,%2,%3}, {%4,%5,%6,%7}, {%8,%9}, {%0,%1,%2,%3};" \
                 : "+f"(c0), "+f"(c1), "+f"(c2), "+f"(c3) \
                 : "r"(a0), "r"(a1), "r"(a2), "r"(a3), "r"(b0), "r"(b1))

// ---------------- dtype sniff: int64 vs int32 indices ------------------------
__global__ void sniff_kernel(const int* __restrict__ u32) {
    int nz = 0;
    for (int i = 1; i < 128; i += 2) nz |= u32[i];
    g_idx_is64 = (nz == 0) ? 1 : 0;
}

// ---------------- gather + L2 normalize + align dot (+fp8 store) -------------
__global__ void gather_norm_kernel(const void* __restrict__ u_raw,
                                   const void* __restrict__ v_raw,
                                   const float* __restrict__ emb) {
    int i = blockIdx.x;
    int t = threadIdx.x;

    long long ui, vi;
    if (g_idx_is64) {
        ui = ((const long long*)u_raw)[i];
        vi = ((const long long*)v_raw)[i];
    } else {
        ui = ((const int*)u_raw)[i];
        vi = ((const int*)v_raw)[i];
    }

    float xu = emb[ui * DIM + t];
    float xv = emb[vi * DIM + t];

    __shared__ float red[8];
    float su2 = xu * xu, sv2 = xv * xv;
    #pragma unroll
    for (int off = 16; off; off >>= 1) {
        su2 += __shfl_down_sync(0xffffffffu, su2, off);
        sv2 += __shfl_down_sync(0xffffffffu, sv2, off);
    }
    int w = t >> 5;
    if ((t & 31) == 0) { red[w] = su2; red[4 + w] = sv2; }
    __syncthreads();
    float ssu = red[0] + red[1] + red[2] + red[3];
    float ssv = red[4] + red[5] + red[6] + red[7];

    float du = fmaxf(sqrtf(ssu), 1e-12f);
    float dv = fmaxf(sqrtf(ssv), 1e-12f);
    float su = xu / du;
    float sv = xv / dv;

    // pack adjacent dims into e4m3x2 (low byte = even dim)
    float su_hi = __shfl_down_sync(0xffffffffu, su, 1);
    float sv_hi = __shfl_down_sync(0xffffffffu, sv, 1);
    if ((t & 1) == 0) {
        uint16_t pu, pv;
        asm("cvt.rn.satfinite.e4m3x2.f32 %0, %1, %2;" : "=h"(pu) : "f"(su_hi), "f"(su));
        asm("cvt.rn.satfinite.e4m3x2.f32 %0, %1, %2;" : "=h"(pv) : "f"(sv_hi), "f"(sv));
        *(uint16_t*)(g_src8 + i * DIM + t) = pu;
        *(uint16_t*)(g_pos8 + i * DIM + t) = pv;
    }

    float dp = su * sv;
    #pragma unroll
    for (int off = 16; off; off >>= 1)
        dp += __shfl_down_sync(0xffffffffu, dp, off);
    __syncthreads();
    if ((t & 31) == 0) red[w] = dp;
    __syncthreads();
    if (t == 0) g_dot[i] = red[0] + red[1] + red[2] + red[3];
}

// ---------------- fused FP8 QMMA Gram + exp row-sum --------------------------
// grid (64, 2): x = 128-row tile, y = matrix (src/pos). 256 threads = 8 warps
// in a 2(m) x 4(n) arrangement; warp tile 64x32 = 4x4 m16n8k32 fragments.
// A tile loaded once; B tiles double-buffered via cp.async.
#define SM_A  0
#define SM_B0 TILE_BYTES
#define SM_B1 (2 * TILE_BYTES)
#define SM_TOTAL (3 * TILE_BYTES)

__device__ __forceinline__ void load_tile(uint32_t sdst, const uint4* eg,
                                          int row0, int tid) {
    // 128 rows x 128B = 1024 x 16B chunks, 4 per thread
    #pragma unroll
    for (int it = 0; it < 4; it++) {
        int idx = tid + it * 256;
        int r = idx >> 3, c = idx & 7;
        CP_ASYNC16(sdst + r * SSTRIDE + c * 16, eg + (row0 + r) * 8 + c);
    }
}

__global__ void __launch_bounds__(256, 1) lse_kernel() {
    extern __shared__ char smem[];
    const uint32_t sbase = smem_u32(smem);
    const int tid = threadIdx.x;
    const int wid = tid >> 5;
    const int lane = tid & 31;
    const int warp_m = wid >> 2;          // 0..1 -> 64 rows each
    const int warp_n = wid & 3;           // 0..3 -> 32 cols each
    const int m_base = warp_m * 64;
    const int n_base = warp_n * 32;

    const uint8_t* e = (blockIdx.y == 0) ? g_src8 : g_pos8;
    const uint4* eg = (const uint4*)e;
    const int r0 = blockIdx.x * 128;

    // prologue: A + B0 in group0, B1 in group1
    load_tile(sbase + SM_A, eg, r0, tid);
    load_tile(sbase + SM_B0, eg, 0, tid);
    CP_COMMIT();
    load_tile(sbase + SM_B1, eg, 128, tid);
    CP_COMMIT();

    // per-lane ldmatrix base offsets (fp8 pairs viewed as b16 elements)
    const int l15 = lane & 15;
    const uint32_t aAddr0 = sbase + SM_A +
        (uint32_t)(m_base + l15) * SSTRIDE + (uint32_t)(lane >> 4) * 16;
    const uint32_t bOff0 =
        (uint32_t)(n_base + (l15 & 7)) * SSTRIDE + (uint32_t)(l15 >> 3) * 16;

    float acc[4][4][4];
    #pragma unroll
    for (int mt = 0; mt < 4; mt++)
        #pragma unroll
        for (int nt = 0; nt < 4; nt++)
            #pragma unroll
            for (int q = 0; q < 4; q++) acc[mt][nt][q] = 0.f;

    float rowsum[8];
    #pragma unroll
    for (int j = 0; j < 8; j++) rowsum[j] = 0.f;

    const float CEX = 2.0f * 1.4426950408889634f;   // exp(2d-2) = 2^(C*d - C)

    for (int i = 0; i < NPTS / 128; i++) {
        if (i < 63) { CP_WAIT1(); } else { CP_WAIT0(); }
        __syncthreads();

        const uint32_t bAddr0 = sbase + ((i & 1) ? SM_B1 : SM_B0) + bOff0;

        #pragma unroll
        for (int k = 0; k < 4; k++) {               // 4 k-steps of 32 fp8
            uint32_t a[4][4];
            #pragma unroll
            for (int mt = 0; mt < 4; mt++)
                LDMATRIX_X4(a[mt][0], a[mt][1], a[mt][2], a[mt][3],
                            aAddr0 + mt * (16 * SSTRIDE) + k * 32);
            uint32_t b[4][2];
            #pragma unroll
            for (int nt = 0; nt < 4; nt++)
                LDMATRIX_X2(b[nt][0], b[nt][1],
                            bAddr0 + nt * (8 * SSTRIDE) + k * 32);
            #pragma unroll
            for (int mt = 0; mt < 4; mt++)
                #pragma unroll
                for (int nt = 0; nt < 4; nt++)
                    MMA_FP8(acc[mt][nt][0], acc[mt][nt][1],
                            acc[mt][nt][2], acc[mt][nt][3],
                            a[mt][0], a[mt][1], a[mt][2], a[mt][3],
                            b[nt][0], b[nt][1]);
        }

        __syncthreads();            // all warps done reading this B buffer
        if (i < 62) {               // overlap next tile copy with epilogue
            load_tile(sbase + ((i & 1) ? SM_B1 : SM_B0), eg, (i + 2) * 128, tid);
            CP_COMMIT();
        }

        // fused epilogue: rowsum += 2^(C*dot - C); re-zero acc
        #pragma unroll
        for (int mt = 0; mt < 4; mt++) {
            float s0 = 0.f, s1 = 0.f;
            #pragma unroll
            for (int nt = 0; nt < 4; nt++) {
                s0 += ex2_approx(fmaf(CEX, acc[mt][nt][0], -CEX));
                s0 += ex2_approx(fmaf(CEX, acc[mt][nt][1], -CEX));
                s1 += ex2_approx(fmaf(CEX, acc[mt][nt][2], -CEX));
                s1 += ex2_approx(fmaf(CEX, acc[mt][nt][3], -CEX));
                acc[mt][nt][0] = 0.f; acc[mt][nt][1] = 0.f;
                acc[mt][nt][2] = 0.f; acc[mt][nt][3] = 0.f;
            }
            rowsum[mt * 2]     += s0;
            rowsum[mt * 2 + 1] += s1;
        }
    }

    // ---- reduction: quad lanes share the same rows ----
    #pragma unroll
    for (int j = 0; j < 8; j++) {
        rowsum[j] += __shfl_xor_sync(0xffffffffu, rowsum[j], 1);
        rowsum[j] += __shfl_xor_sync(0xffffffffu, rowsum[j], 2);
    }

    float* red = (float*)smem;            // reuse A region: red[warp_n][128]
    if ((lane & 3) == 0) {
        #pragma unroll
        for (int mt = 0; mt < 4; mt++) {
            int row = m_base + mt * 16 + (lane >> 2);
            red[warp_n * 128 + row]     = rowsum[mt * 2];
            red[warp_n * 128 + row + 8] = rowsum[mt * 2 + 1];
        }
    }
    __syncthreads();
    if (tid < 128) {
        float s = red[tid] + red[128 + tid] + red[256 + tid] + red[384 + tid];
        red[512 + tid] = logf(s);
    }
    __syncthreads();
    if (tid == 0) {
        float ssum = 0.f;
        #pragma unroll
        for (int k = 0; k < 128; k++) ssum += red[512 + k];
        g_lse_partial[blockIdx.y * 64 + blockIdx.x] = ssum;
    }
}

// ---------------- finalize ----------------------------------------------------
__global__ void finalize_kernel(float* __restrict__ out) {
    int tid = threadIdx.x;
    float a = 0.f, l = 0.f;
    for (int i = tid; i < NPTS; i += 256) a += g_dot[i];
    for (int i = tid; i < 128; i += 256)  l += g_lse_partial[i];
    __shared__ float ra[256], rl[256];
    ra[tid] = a; rl[tid] = l;
    __syncthreads();
    for (int s = 128; s; s >>= 1) {
        if (tid < s) { ra[tid] += ra[tid + s]; rl[tid] += rl[tid + s]; }
        __syncthreads();
    }
    if (tid == 0) {
        float align_mean = ra[0] / (float)NPTS;
        float align = 2.0f - 2.0f * align_mean;
        float unif  = rl[0] / (float)NPTS;
        out[0] = 4.0f * align + 2.0f * unif;
    }
}

// ---------------- launch ------------------------------------------------------
extern "C" void kernel_launch(void* const* d_in, const int* in_sizes, int n_in,
                              void* d_out, int out_size) {
    const void*  u   = d_in[0];
    const void*  v   = d_in[1];
    const float* emb = (const float*)d_in[2];

    cudaFuncSetAttribute(lse_kernel,
                         cudaFuncAttributeMaxDynamicSharedMemorySize, SM_TOTAL);

    sniff_kernel<<<1, 1>>>((const int*)u);
    gather_norm_kernel<<<NPTS, DIM>>>(u, v, emb);
    lse_kernel<<<dim3(64, 2), 256, SM_TOTAL>>>();
    finalize_kernel<<<1, 256>>>((float*)d_out);
}

// round 7
// speedup vs baseline: 1.7637x; 1.7637x over previous
#include <cuda_runtime.h>
#include <cuda_bf16.h>
#include <cstdint>

#define NPTS 8192
#define DIM 128
#define SSTRIDE 272                   // bf16 tile row stride bytes (136 bf16)
#define TILE_BYTES (128 * SSTRIDE)    // 34816

// ---------------- scratch (device globals; no allocations allowed) ----------
__device__ __nv_bfloat16 g_src[NPTS * DIM];
__device__ __nv_bfloat16 g_pos[NPTS * DIM];
__device__ float g_dot[NPTS];
__device__ float g_rowsum[2 * NPTS];            // own-tile row sums of exp
__device__ float g_cross[2 * 64 * 33 * 128];    // [my][bj][slot t][row] col-sum partials
__device__ float g_lse_partial[128];            // [my(2)][row-block(64)]
__device__ int   g_idx_is64;

// ---------------- PTX helpers ------------------------------------------------
__device__ __forceinline__ uint32_t smem_u32(const void* p) {
    uint32_t a;
    asm("{ .reg .u64 t; cvta.to.shared.u64 t, %1; cvt.u32.u64 %0, t; }"
        : "=r"(a) : "l"(p));
    return a;
}

__device__ __forceinline__ float ex2_approx(float x) {
    float y;
    asm("ex2.approx.f32 %0, %1;" : "=f"(y) : "f"(x));
    return y;
}

#define CP_ASYNC16(dst, src) \
    asm volatile("cp.async.cg.shared.global [%0], [%1], 16;" :: "r"(dst), "l"(src) : "memory")
#define CP_COMMIT() asm volatile("cp.async.commit_group;" ::: "memory")
#define CP_WAIT1()  asm volatile("cp.async.wait_group 1;" ::: "memory")
#define CP_WAIT0()  asm volatile("cp.async.wait_group 0;" ::: "memory")

#define LDMATRIX_X4(r0, r1, r2, r3, addr) \
    asm volatile("ldmatrix.sync.aligned.m8n8.x4.shared.b16 {%0,%1,%2,%3}, [%4];" \
                 : "=r"(r0), "=r"(r1), "=r"(r2), "=r"(r3) : "r"(addr))
#define LDMATRIX_X2(r0, r1, addr) \
    asm volatile("ldmatrix.sync.aligned.m8n8.x2.shared.b16 {%0,%1}, [%2];" \
                 : "=r"(r0), "=r"(r1) : "r"(addr))

#define MMA16816(c0, c1, c2, c3, a0, a1, a2, a3, b0, b1) \
    asm volatile("mma.sync.aligned.m16n8k16.row.col.f32.bf16.bf16.f32 " \
                 "{%0,%1,%2,%3}, {%4,%5,%6,%7}, {%8,%9}, {%0,%1,%2,%3};" \
                 : "+f"(c0), "+f"(c1), "+f"(c2), "+f"(c3) \
                 : "r"(a0), "r"(a1), "r"(a2), "r"(a3), "r"(b0), "r"(b1))

// ---------------- dtype sniff: int64 vs int32 indices ------------------------
__global__ void sniff_kernel(const int* __restrict__ u32) {
    int nz = 0;
    for (int i = 1; i < 128; i += 2) nz |= u32[i];
    g_idx_is64 = (nz == 0) ? 1 : 0;
}

// ---------------- gather + L2 normalize + align dot (+bf16 store) ------------
__global__ void gather_norm_kernel(const void* __restrict__ u_raw,
                                   const void* __restrict__ v_raw,
                                   const float* __restrict__ emb) {
    int i = blockIdx.x;
    int t = threadIdx.x;

    long long ui, vi;
    if (g_idx_is64) {
        ui = ((const long long*)u_raw)[i];
        vi = ((const long long*)v_raw)[i];
    } else {
        ui = ((const int*)u_raw)[i];
        vi = ((const int*)v_raw)[i];
    }

    float xu = emb[ui * DIM + t];
    float xv = emb[vi * DIM + t];

    __shared__ float red[8];
    float su2 = xu * xu, sv2 = xv * xv;
    #pragma unroll
    for (int off = 16; off; off >>= 1) {
        su2 += __shfl_down_sync(0xffffffffu, su2, off);
        sv2 += __shfl_down_sync(0xffffffffu, sv2, off);
    }
    int w = t >> 5;
    if ((t & 31) == 0) { red[w] = su2; red[4 + w] = sv2; }
    __syncthreads();
    float ssu = red[0] + red[1] + red[2] + red[3];
    float ssv = red[4] + red[5] + red[6] + red[7];

    float du = fmaxf(sqrtf(ssu), 1e-12f);
    float dv = fmaxf(sqrtf(ssv), 1e-12f);
    float su = xu / du;
    float sv = xv / dv;

    g_src[i * DIM + t] = __float2bfloat16(su);
    g_pos[i * DIM + t] = __float2bfloat16(sv);

    float dp = su * sv;
    #pragma unroll
    for (int off = 16; off; off >>= 1)
        dp += __shfl_down_sync(0xffffffffu, dp, off);
    __syncthreads();
    if ((t & 31) == 0) red[w] = dp;
    __syncthreads();
    if (t == 0) g_dot[i] = red[0] + red[1] + red[2] + red[3];
}

// ---------------- fused HMMA Gram (symmetric half) + exp sums ----------------
// grid (64, 2): x = row-block bi, y = matrix. 256 threads = 8 warps, 2(m)x4(n).
// Tournament schedule: CTA bi computes tiles (bi, (bi+t)%64), t=0..NT-1,
// NT = 32 (+1 if bi<32). Each unordered tile pair computed exactly once.
// Row sums kept locally; column sums (= mirrored tile's row sums) written to
// g_cross[my][bj][t][*]. SMEM: A | B0 | B1 | cs_sm(8x32 f32).
#define SM_A  0
#define SM_B0 TILE_BYTES
#define SM_B1 (2 * TILE_BYTES)
#define SM_CS (3 * TILE_BYTES)
#define SM_TOTAL (3 * TILE_BYTES + 8 * 32 * 4)

__device__ __forceinline__ void load_tile(uint32_t sdst, const uint4* eg,
                                          int row0, int tid) {
    #pragma unroll
    for (int it = 0; it < 8; it++) {
        int idx = tid + it * 256;
        int r = idx >> 4, c = idx & 15;
        CP_ASYNC16(sdst + r * SSTRIDE + c * 16, eg + (row0 + r) * 16 + c);
    }
}

__global__ void __launch_bounds__(256, 1) lse_kernel() {
    extern __shared__ char smem[];
    const uint32_t sbase = smem_u32(smem);
    const int tid = threadIdx.x;
    const int wid = tid >> 5;
    const int lane = tid & 31;
    const int warp_m = wid >> 2;          // 0..1 -> 64 rows each
    const int warp_n = wid & 3;           // 0..3 -> 32 cols each
    const int m_base = warp_m * 64;
    const int n_base = warp_n * 32;
    const int bi = blockIdx.x;
    const int my = blockIdx.y;
    const int NT = 32 + (bi < 32 ? 1 : 0);

    const __nv_bfloat16* e = (my == 0) ? g_src : g_pos;
    const uint4* eg = (const uint4*)e;
    float* cs_sm = (float*)(smem + SM_CS);

    // prologue: A + B(t=0) in group0, B(t=1) in group1
    load_tile(sbase + SM_A, eg, bi * 128, tid);
    load_tile(sbase + SM_B0, eg, bi * 128, tid);           // t=0: diagonal block
    CP_COMMIT();
    load_tile(sbase + SM_B1, eg, ((bi + 1) & 63) * 128, tid);
    CP_COMMIT();

    const int l15 = lane & 15;
    const uint32_t aAddr0 = sbase + SM_A +
        (uint32_t)(m_base + l15) * SSTRIDE + (uint32_t)(lane >> 4) * 16;
    const uint32_t bOff0 =
        (uint32_t)(n_base + (l15 & 7)) * SSTRIDE + (uint32_t)(l15 >> 3) * 16;

    float acc[4][4][4];
    #pragma unroll
    for (int mt = 0; mt < 4; mt++)
        #pragma unroll
        for (int nt = 0; nt < 4; nt++)
            #pragma unroll
            for (int q = 0; q < 4; q++) acc[mt][nt][q] = 0.f;

    float rowsum[8];
    #pragma unroll
    for (int j = 0; j < 8; j++) rowsum[j] = 0.f;

    const float CEX = 2.0f * 1.4426950408889634f;   // exp(2d-2) = 2^(CEX*d - CEX)

    for (int t = 0; t < NT; t++) {
        if (t < NT - 1) { CP_WAIT1(); } else { CP_WAIT0(); }
        __syncthreads();

        const uint32_t bAddr0 = sbase + ((t & 1) ? SM_B1 : SM_B0) + bOff0;

        #pragma unroll
        for (int k = 0; k < 8; k++) {
            uint32_t a[4][4];
            #pragma unroll
            for (int mt = 0; mt < 4; mt++)
                LDMATRIX_X4(a[mt][0], a[mt][1], a[mt][2], a[mt][3],
                            aAddr0 + mt * (16 * SSTRIDE) + k * 32);
            uint32_t b[4][2];
            #pragma unroll
            for (int nt = 0; nt < 4; nt++)
                LDMATRIX_X2(b[nt][0], b[nt][1],
                            bAddr0 + nt * (8 * SSTRIDE) + k * 32);
            #pragma unroll
            for (int mt = 0; mt < 4; mt++)
                #pragma unroll
                for (int nt = 0; nt < 4; nt++)
                    MMA16816(acc[mt][nt][0], acc[mt][nt][1],
                             acc[mt][nt][2], acc[mt][nt][3],
                             a[mt][0], a[mt][1], a[mt][2], a[mt][3],
                             b[nt][0], b[nt][1]);
        }

        __syncthreads();            // all warps done reading this B buffer
        if (t + 2 < NT) {
            load_tile(sbase + ((t & 1) ? SM_B1 : SM_B0), eg,
                      ((bi + t + 2) & 63) * 128, tid);
            CP_COMMIT();
        }

        // epilogue: ev = exp(2d-2); row sums always, col sums for t>0
        float cs[4][2];
        #pragma unroll
        for (int nt = 0; nt < 4; nt++) { cs[nt][0] = 0.f; cs[nt][1] = 0.f; }

        #pragma unroll
        for (int mt = 0; mt < 4; mt++) {
            float s0 = 0.f, s1 = 0.f;
            #pragma unroll
            for (int nt = 0; nt < 4; nt++) {
                float e0 = ex2_approx(fmaf(CEX, acc[mt][nt][0], -CEX));
                float e1 = ex2_approx(fmaf(CEX, acc[mt][nt][1], -CEX));
                float e2 = ex2_approx(fmaf(CEX, acc[mt][nt][2], -CEX));
                float e3 = ex2_approx(fmaf(CEX, acc[mt][nt][3], -CEX));
                s0 += e0 + e1;
                s1 += e2 + e3;
                cs[nt][0] += e0 + e2;
                cs[nt][1] += e1 + e3;
                acc[mt][nt][0] = 0.f; acc[mt][nt][1] = 0.f;
                acc[mt][nt][2] = 0.f; acc[mt][nt][3] = 0.f;
            }
            rowsum[mt * 2]     += s0;
            rowsum[mt * 2 + 1] += s1;
        }

        if (t != 0) {
            // reduce col partials over the 8 row-groups (lane>>2)
            #pragma unroll
            for (int nt = 0; nt < 4; nt++) {
                #pragma unroll
                for (int j = 0; j < 2; j++) {
                    cs[nt][j] += __shfl_xor_sync(0xffffffffu, cs[nt][j], 4);
                    cs[nt][j] += __shfl_xor_sync(0xffffffffu, cs[nt][j], 8);
                    cs[nt][j] += __shfl_xor_sync(0xffffffffu, cs[nt][j], 16);
                }
            }
            if (lane < 4) {
                #pragma unroll
                for (int nt = 0; nt < 4; nt++) {
                    cs_sm[wid * 32 + nt * 8 + lane * 2]     = cs[nt][0];
                    cs_sm[wid * 32 + nt * 8 + lane * 2 + 1] = cs[nt][1];
                }
            }
            __syncthreads();
            if (tid < 128) {
                int wn = tid >> 5, c = tid & 31;
                float v = cs_sm[wn * 32 + c] + cs_sm[(4 + wn) * 32 + c];
                int bj = (bi + t) & 63;
                g_cross[((my * 64 + bj) * 33 + t) * 128 + tid] = v;
            }
        }
    }

    // ---- own row sums: quad lanes share rows ----
    #pragma unroll
    for (int j = 0; j < 8; j++) {
        rowsum[j] += __shfl_xor_sync(0xffffffffu, rowsum[j], 1);
        rowsum[j] += __shfl_xor_sync(0xffffffffu, rowsum[j], 2);
    }

    float* red = (float*)smem;            // reuse A region
    __syncthreads();
    if ((lane & 3) == 0) {
        #pragma unroll
        for (int mt = 0; mt < 4; mt++) {
            int row = m_base + mt * 16 + (lane >> 2);
            red[warp_n * 128 + row]     = rowsum[mt * 2];
            red[warp_n * 128 + row + 8] = rowsum[mt * 2 + 1];
        }
    }
    __syncthreads();
    if (tid < 128) {
        float s = red[tid] + red[128 + tid] + red[256 + tid] + red[384 + tid];
        g_rowsum[my * NPTS + bi * 128 + tid] = s;
    }
}

// ---------------- per-row combine + log + block partial ----------------------
__global__ void reduce_kernel() {
    const int bi = blockIdx.x;
    const int my = blockIdx.y;
    const int r = threadIdx.x;           // 0..127

    float s = g_rowsum[my * NPTS + bi * 128 + r];
    const float* cr = &g_cross[(my * 64 + bi) * 33 * 128 + r];
    #pragma unroll 4
    for (int t = 1; t <= 31; t++) s += cr[t * 128];
    if (bi >= 32) s += cr[32 * 128];

    __shared__ float red[128];
    red[r] = logf(s);
    __syncthreads();
    for (int st = 64; st; st >>= 1) {
        if (r < st) red[r] += red[r + st];
        __syncthreads();
    }
    if (r == 0) g_lse_partial[my * 64 + bi] = red[0];
}

// ---------------- finalize ----------------------------------------------------
__global__ void finalize_kernel(float* __restrict__ out) {
    int tid = threadIdx.x;
    float a = 0.f, l = 0.f;
    for (int i = tid; i < NPTS; i += 256) a += g_dot[i];
    for (int i = tid; i < 128; i += 256)  l += g_lse_partial[i];
    __shared__ float ra[256], rl[256];
    ra[tid] = a; rl[tid] = l;
    __syncthreads();
    for (int s = 128; s; s >>= 1) {
        if (tid < s) { ra[tid] += ra[tid + s]; rl[tid] += rl[tid + s]; }
        __syncthreads();
    }
    if (tid == 0) {
        float align_mean = ra[0] / (float)NPTS;
        float align = 2.0f - 2.0f * align_mean;
        float unif  = rl[0] / (float)NPTS;
        out[0] = 4.0f * align + 2.0f * unif;
    }
}

// ---------------- launch ------------------------------------------------------
extern "C" void kernel_launch(void* const* d_in, const int* in_sizes, int n_in,
                              void* d_out, int out_size) {
    const void*  u   = d_in[0];
    const void*  v   = d_in[1];
    const float* emb = (const float*)d_in[2];

    cudaFuncSetAttribute(lse_kernel,
                         cudaFuncAttributeMaxDynamicSharedMemorySize, SM_TOTAL);

    sniff_kernel<<<1, 1>>>((const int*)u);
    gather_norm_kernel<<<NPTS, DIM>>>(u, v, emb);
    lse_kernel<<<dim3(64, 2), 256, SM_TOTAL>>>();
    reduce_kernel<<<dim3(64, 2), 128>>>();
    finalize_kernel<<<1, 256>>>((float*)d_out);
}

// round 8
// speedup vs baseline: 1.7994x; 1.0202x over previous
#include <cuda_runtime.h>
#include <cuda_bf16.h>
#include <cstdint>

#define NPTS 8192
#define DIM 128
#define SSTRIDE 272                   // bf16 tile row stride bytes (136 bf16)
#define TILE_BYTES (128 * SSTRIDE)    // 34816

// ---------------- scratch (device globals; no allocations allowed) ----------
__device__ __nv_bfloat16 g_src[NPTS * DIM];
__device__ __nv_bfloat16 g_pos[NPTS * DIM];
__device__ float g_dot[NPTS];
__device__ float g_rowsum[2 * 2 * NPTS];        // [my][z][bi][row] own row sums
__device__ float g_cross[2 * 64 * 33 * 128];    // [my][bj][slot t][row] col sums
__device__ float g_lse_partial[128];            // [my(2)][row-block(64)]
__device__ float g_dotp[64];                    // per row-block align-dot partial
__device__ int   g_idx_is64;

// ---------------- PTX helpers ------------------------------------------------
__device__ __forceinline__ uint32_t smem_u32(const void* p) {
    uint32_t a;
    asm("{ .reg .u64 t; cvta.to.shared.u64 t, %1; cvt.u32.u64 %0, t; }"
        : "=r"(a) : "l"(p));
    return a;
}

__device__ __forceinline__ float ex2_approx(float x) {
    float y;
    asm("ex2.approx.f32 %0, %1;" : "=f"(y) : "f"(x));
    return y;
}

#define CP_ASYNC16(dst, src) \
    asm volatile("cp.async.cg.shared.global [%0], [%1], 16;" :: "r"(dst), "l"(src) : "memory")
#define CP_COMMIT() asm volatile("cp.async.commit_group;" ::: "memory")
#define CP_WAIT1()  asm volatile("cp.async.wait_group 1;" ::: "memory")
#define CP_WAIT0()  asm volatile("cp.async.wait_group 0;" ::: "memory")

#define LDMATRIX_X4(r0, r1, r2, r3, addr) \
    asm volatile("ldmatrix.sync.aligned.m8n8.x4.shared.b16 {%0,%1,%2,%3}, [%4];" \
                 : "=r"(r0), "=r"(r1), "=r"(r2), "=r"(r3) : "r"(addr))
#define LDMATRIX_X2(r0, r1, addr) \
    asm volatile("ldmatrix.sync.aligned.m8n8.x2.shared.b16 {%0,%1}, [%2];" \
                 : "=r"(r0), "=r"(r1) : "r"(addr))

#define MMA16816(c0, c1, c2, c3, a0, a1, a2, a3, b0, b1) \
    asm volatile("mma.sync.aligned.m16n8k16.row.col.f32.bf16.bf16.f32 " \
                 "{%0,%1,%2,%3}, {%4,%5,%6,%7}, {%8,%9}, {%0,%1,%2,%3};" \
                 : "+f"(c0), "+f"(c1), "+f"(c2), "+f"(c3) \
                 : "r"(a0), "r"(a1), "r"(a2), "r"(a3), "r"(b0), "r"(b1))

// ---------------- dtype sniff: int64 vs int32 indices ------------------------
__global__ void sniff_kernel(const int* __restrict__ u32) {
    int nz = 0;
    for (int i = 1; i < 128; i += 2) nz |= u32[i];
    g_idx_is64 = (nz == 0) ? 1 : 0;
}

// ---------------- gather + L2 normalize + align dot (+bf16 store) ------------
__global__ void gather_norm_kernel(const void* __restrict__ u_raw,
                                   const void* __restrict__ v_raw,
                                   const float* __restrict__ emb) {
    int i = blockIdx.x;
    int t = threadIdx.x;

    long long ui, vi;
    if (g_idx_is64) {
        ui = ((const long long*)u_raw)[i];
        vi = ((const long long*)v_raw)[i];
    } else {
        ui = ((const int*)u_raw)[i];
        vi = ((const int*)v_raw)[i];
    }

    float xu = emb[ui * DIM + t];
    float xv = emb[vi * DIM + t];

    __shared__ float red[8];
    float su2 = xu * xu, sv2 = xv * xv;
    #pragma unroll
    for (int off = 16; off; off >>= 1) {
        su2 += __shfl_down_sync(0xffffffffu, su2, off);
        sv2 += __shfl_down_sync(0xffffffffu, sv2, off);
    }
    int w = t >> 5;
    if ((t & 31) == 0) { red[w] = su2; red[4 + w] = sv2; }
    __syncthreads();
    float ssu = red[0] + red[1] + red[2] + red[3];
    float ssv = red[4] + red[5] + red[6] + red[7];

    float du = fmaxf(sqrtf(ssu), 1e-12f);
    float dv = fmaxf(sqrtf(ssv), 1e-12f);
    float su = xu / du;
    float sv = xv / dv;

    g_src[i * DIM + t] = __float2bfloat16(su);
    g_pos[i * DIM + t] = __float2bfloat16(sv);

    float dp = su * sv;
    #pragma unroll
    for (int off = 16; off; off >>= 1)
        dp += __shfl_down_sync(0xffffffffu, dp, off);
    __syncthreads();
    if ((t & 31) == 0) red[w] = dp;
    __syncthreads();
    if (t == 0) g_dot[i] = red[0] + red[1] + red[2] + red[3];
}

// ---------------- fused HMMA Gram (symmetric half) + exp sums ----------------
// grid (64, 2, 2): x = row-block bi, y = matrix, z = t-range half.
// Tournament: CTA (bi,*,z) computes tiles (bi, (bi+t)%64) for t in its half of
// [0, NT), NT = 32 (+1 if bi<32). Each unordered tile pair computed once.
// 2 CTAs/SM (206KB smem total) to fill MMA-issue bubbles.
#define SM_A  0
#define SM_B0 TILE_BYTES
#define SM_B1 (2 * TILE_BYTES)
#define SM_CS (3 * TILE_BYTES)
#define SM_TOTAL (3 * TILE_BYTES + 8 * 32 * 4)

__device__ __forceinline__ void load_tile(uint32_t sdst, const uint4* eg,
                                          int row0, int tid) {
    #pragma unroll
    for (int it = 0; it < 8; it++) {
        int idx = tid + it * 256;
        int r = idx >> 4, c = idx & 15;
        CP_ASYNC16(sdst + r * SSTRIDE + c * 16, eg + (row0 + r) * 16 + c);
    }
}

__global__ void __launch_bounds__(256, 2) lse_kernel() {
    extern __shared__ char smem[];
    const uint32_t sbase = smem_u32(smem);
    const int tid = threadIdx.x;
    const int wid = tid >> 5;
    const int lane = tid & 31;
    const int warp_m = wid >> 2;          // 0..1 -> 64 rows each
    const int warp_n = wid & 3;           // 0..3 -> 32 cols each
    const int m_base = warp_m * 64;
    const int n_base = warp_n * 32;
    const int bi = blockIdx.x;
    const int my = blockIdx.y;
    const int zz = blockIdx.z;
    const int NT = 32 + (bi < 32 ? 1 : 0);
    const int t0 = zz * 16;
    const int tEnd = zz == 0 ? 16 : NT;

    const __nv_bfloat16* e = (my == 0) ? g_src : g_pos;
    const uint4* eg = (const uint4*)e;
    float* cs_sm = (float*)(smem + SM_CS);

    // prologue: A + B(t0) in group0, B(t0+1) in group1
    load_tile(sbase + SM_A, eg, bi * 128, tid);
    load_tile(sbase + SM_B0, eg, ((bi + t0) & 63) * 128, tid);
    CP_COMMIT();
    load_tile(sbase + SM_B1, eg, ((bi + t0 + 1) & 63) * 128, tid);
    CP_COMMIT();

    const int l15 = lane & 15;
    const uint32_t aAddr0 = sbase + SM_A +
        (uint32_t)(m_base + l15) * SSTRIDE + (uint32_t)(lane >> 4) * 16;
    const uint32_t bOff0 =
        (uint32_t)(n_base + (l15 & 7)) * SSTRIDE + (uint32_t)(l15 >> 3) * 16;

    float acc[4][4][4];
    #pragma unroll
    for (int mt = 0; mt < 4; mt++)
        #pragma unroll
        for (int nt = 0; nt < 4; nt++)
            #pragma unroll
            for (int q = 0; q < 4; q++) acc[mt][nt][q] = 0.f;

    float rowsum[8];
    #pragma unroll
    for (int j = 0; j < 8; j++) rowsum[j] = 0.f;

    const float CEX = 2.0f * 1.4426950408889634f;   // exp(2d-2) = 2^(CEX*d - CEX)

    for (int t = t0; t < tEnd; t++) {
        if (t < tEnd - 1) { CP_WAIT1(); } else { CP_WAIT0(); }
        __syncthreads();

        const uint32_t bAddr0 = sbase + ((t & 1) ? SM_B1 : SM_B0) + bOff0;

        #pragma unroll
        for (int k = 0; k < 8; k++) {
            uint32_t a[4][4];
            #pragma unroll
            for (int mt = 0; mt < 4; mt++)
                LDMATRIX_X4(a[mt][0], a[mt][1], a[mt][2], a[mt][3],
                            aAddr0 + mt * (16 * SSTRIDE) + k * 32);
            uint32_t b[4][2];
            #pragma unroll
            for (int nt = 0; nt < 4; nt++)
                LDMATRIX_X2(b[nt][0], b[nt][1],
                            bAddr0 + nt * (8 * SSTRIDE) + k * 32);
            #pragma unroll
            for (int mt = 0; mt < 4; mt++)
                #pragma unroll
                for (int nt = 0; nt < 4; nt++)
                    MMA16816(acc[mt][nt][0], acc[mt][nt][1],
                             acc[mt][nt][2], acc[mt][nt][3],
                             a[mt][0], a[mt][1], a[mt][2], a[mt][3],
                             b[nt][0], b[nt][1]);
        }

        __syncthreads();            // all warps done reading this B buffer
        if (t + 2 < tEnd) {
            load_tile(sbase + ((t & 1) ? SM_B1 : SM_B0), eg,
                      ((bi + t + 2) & 63) * 128, tid);
            CP_COMMIT();
        }

        // epilogue: ev = exp(2d-2); row sums always, col sums for t>0
        float cs[4][2];
        #pragma unroll
        for (int nt = 0; nt < 4; nt++) { cs[nt][0] = 0.f; cs[nt][1] = 0.f; }

        #pragma unroll
        for (int mt = 0; mt < 4; mt++) {
            float s0 = 0.f, s1 = 0.f;
            #pragma unroll
            for (int nt = 0; nt < 4; nt++) {
                float e0 = ex2_approx(fmaf(CEX, acc[mt][nt][0], -CEX));
                float e1 = ex2_approx(fmaf(CEX, acc[mt][nt][1], -CEX));
                float e2 = ex2_approx(fmaf(CEX, acc[mt][nt][2], -CEX));
                float e3 = ex2_approx(fmaf(CEX, acc[mt][nt][3], -CEX));
                s0 += e0 + e1;
                s1 += e2 + e3;
                cs[nt][0] += e0 + e2;
                cs[nt][1] += e1 + e3;
                acc[mt][nt][0] = 0.f; acc[mt][nt][1] = 0.f;
                acc[mt][nt][2] = 0.f; acc[mt][nt][3] = 0.f;
            }
            rowsum[mt * 2]     += s0;
            rowsum[mt * 2 + 1] += s1;
        }

        if (t != 0) {
            // reduce col partials over the 8 row-groups (lane>>2)
            #pragma unroll
            for (int nt = 0; nt < 4; nt++) {
                #pragma unroll
                for (int j = 0; j < 2; j++) {
                    cs[nt][j] += __shfl_xor_sync(0xffffffffu, cs[nt][j], 4);
                    cs[nt][j] += __shfl_xor_sync(0xffffffffu, cs[nt][j], 8);
                    cs[nt][j] += __shfl_xor_sync(0xffffffffu, cs[nt][j], 16);
                }
            }
            if (lane < 4) {
                #pragma unroll
                for (int nt = 0; nt < 4; nt++) {
                    cs_sm[wid * 32 + nt * 8 + lane * 2]     = cs[nt][0];
                    cs_sm[wid * 32 + nt * 8 + lane * 2 + 1] = cs[nt][1];
                }
            }
            __syncthreads();
            if (tid < 128) {
                int wn = tid >> 5, c = tid & 31;
                float v = cs_sm[wn * 32 + c] + cs_sm[(4 + wn) * 32 + c];
                int bj = (bi + t) & 63;
                g_cross[((my * 64 + bj) * 33 + t) * 128 + tid] = v;
            }
        }
    }

    // ---- own row sums: quad lanes share rows ----
    #pragma unroll
    for (int j = 0; j < 8; j++) {
        rowsum[j] += __shfl_xor_sync(0xffffffffu, rowsum[j], 1);
        rowsum[j] += __shfl_xor_sync(0xffffffffu, rowsum[j], 2);
    }

    float* red = (float*)smem;            // reuse A region
    __syncthreads();
    if ((lane & 3) == 0) {
        #pragma unroll
        for (int mt = 0; mt < 4; mt++) {
            int row = m_base + mt * 16 + (lane >> 2);
            red[warp_n * 128 + row]     = rowsum[mt * 2];
            red[warp_n * 128 + row + 8] = rowsum[mt * 2 + 1];
        }
    }
    __syncthreads();
    if (tid < 128) {
        float s = red[tid] + red[128 + tid] + red[256 + tid] + red[384 + tid];
        g_rowsum[((my * 2 + zz) * 64 + bi) * 128 + tid] = s;
    }
}

// ---------------- per-row combine + log + block partial (+dot partial) -------
__global__ void reduce_kernel() {
    const int bi = blockIdx.x;
    const int my = blockIdx.y;
    const int tid = threadIdx.x;         // 0..255
    const int r = tid & 127;
    const int h = tid >> 7;

    const float* cr = &g_cross[(my * 64 + bi) * 33 * 128 + r];
    float s = 0.f;
    if (h == 0) {
        s += g_rowsum[((my * 2 + 0) * 64 + bi) * 128 + r];
        s += g_rowsum[((my * 2 + 1) * 64 + bi) * 128 + r];
        #pragma unroll 4
        for (int t = 1; t <= 16; t++) s += cr[t * 128];
    } else {
        #pragma unroll 4
        for (int t = 17; t <= 31; t++) s += cr[t * 128];
        if (bi >= 32) s += cr[32 * 128];
    }

    __shared__ float sm2[256];
    sm2[tid] = s;
    __syncthreads();
    if (h == 0) sm2[r] = logf(sm2[r] + sm2[r + 128]);
    __syncthreads();
    for (int st = 64; st; st >>= 1) {
        if (tid < st) sm2[tid] += sm2[tid + st];
        __syncthreads();
    }
    if (tid == 0) g_lse_partial[my * 64 + bi] = sm2[0];

    if (my == 0) {
        sm2[tid] = (tid < 128) ? g_dot[bi * 128 + tid] : 0.f;
        __syncthreads();
        for (int st = 128; st; st >>= 1) {
            if (tid < st) sm2[tid] += sm2[tid + st];
            __syncthreads();
        }
        if (tid == 0) g_dotp[bi] = sm2[0];
    }
}

// ---------------- finalize ----------------------------------------------------
__global__ void finalize_kernel(float* __restrict__ out) {
    int tid = threadIdx.x;               // 128 threads
    float l = g_lse_partial[tid];
    float a = (tid < 64) ? g_dotp[tid] : 0.f;
    __shared__ float ra[128], rl[128];
    ra[tid] = a; rl[tid] = l;
    __syncthreads();
    for (int s = 64; s; s >>= 1) {
        if (tid < s) { ra[tid] += ra[tid + s]; rl[tid] += rl[tid + s]; }
        __syncthreads();
    }
    if (tid == 0) {
        float align_mean = ra[0] / (float)NPTS;
        float align = 2.0f - 2.0f * align_mean;
        float unif  = rl[0] / (float)NPTS;
        out[0] = 4.0f * align + 2.0f * unif;
    }
}

// ---------------- launch ------------------------------------------------------
extern "C" void kernel_launch(void* const* d_in, const int* in_sizes, int n_in,
                              void* d_out, int out_size) {
    const void*  u   = d_in[0];
    const void*  v   = d_in[1];
    const float* emb = (const float*)d_in[2];

    cudaFuncSetAttribute(lse_kernel,
                         cudaFuncAttributeMaxDynamicSharedMemorySize, SM_TOTAL);

    sniff_kernel<<<1, 1>>>((const int*)u);
    gather_norm_kernel<<<NPTS, DIM>>>(u, v, emb);
    lse_kernel<<<dim3(64, 2, 2), 256, SM_TOTAL>>>();
    reduce_kernel<<<dim3(64, 2), 256>>>();
    finalize_kernel<<<1, 128>>>((float*)d_out);
}

// round 9
// speedup vs baseline: 1.8648x; 1.0364x over previous
#include <cuda_runtime.h>
#include <cuda_bf16.h>
#include <cstdint>

#define NPTS 8192
#define DIM 128
#define SSTRIDE 272                   // bf16 tile row stride bytes (136 bf16)
#define TILE_BYTES (128 * SSTRIDE)    // 34816

// ---------------- scratch (device globals; no allocations allowed) ----------
__device__ __nv_bfloat16 g_src[NPTS * DIM];
__device__ __nv_bfloat16 g_pos[NPTS * DIM];
__device__ float g_dot[NPTS];
__device__ float g_rowsum[2 * 2 * NPTS];            // [my][z][bi][row]
__device__ float g_cross[2 * 64 * 33 * 2 * 128];    // [my][bj][t][warp_m][row]
__device__ float g_lse_partial[128];                // [my(2)][row-block(64)]
__device__ float g_dotp[64];
__device__ int   g_idx_is64;

// ---------------- PTX helpers ------------------------------------------------
__device__ __forceinline__ uint32_t smem_u32(const void* p) {
    uint32_t a;
    asm("{ .reg .u64 t; cvta.to.shared.u64 t, %1; cvt.u32.u64 %0, t; }"
        : "=r"(a) : "l"(p));
    return a;
}

__device__ __forceinline__ float ex2_approx(float x) {
    float y;
    asm("ex2.approx.f32 %0, %1;" : "=f"(y) : "f"(x));
    return y;
}

#define CP_ASYNC16(dst, src) \
    asm volatile("cp.async.cg.shared.global [%0], [%1], 16;" :: "r"(dst), "l"(src) : "memory")
#define CP_COMMIT() asm volatile("cp.async.commit_group;" ::: "memory")
#define CP_WAIT1()  asm volatile("cp.async.wait_group 1;" ::: "memory")
#define CP_WAIT0()  asm volatile("cp.async.wait_group 0;" ::: "memory")

#define LDMATRIX_X4(r0, r1, r2, r3, addr) \
    asm volatile("ldmatrix.sync.aligned.m8n8.x4.shared.b16 {%0,%1,%2,%3}, [%4];" \
                 : "=r"(r0), "=r"(r1), "=r"(r2), "=r"(r3) : "r"(addr))
#define LDMATRIX_X2(r0, r1, addr) \
    asm volatile("ldmatrix.sync.aligned.m8n8.x2.shared.b16 {%0,%1}, [%2];" \
                 : "=r"(r0), "=r"(r1) : "r"(addr))

#define MMA16816(c0, c1, c2, c3, a0, a1, a2, a3, b0, b1) \
    asm volatile("mma.sync.aligned.m16n8k16.row.col.f32.bf16.bf16.f32 " \
                 "{%0,%1,%2,%3}, {%4,%5,%6,%7}, {%8,%9}, {%0,%1,%2,%3};" \
                 : "+f"(c0), "+f"(c1), "+f"(c2), "+f"(c3) \
                 : "r"(a0), "r"(a1), "r"(a2), "r"(a3), "r"(b0), "r"(b1))

// ---------------- dtype sniff: int64 vs int32 indices ------------------------
__global__ void sniff_kernel(const int* __restrict__ u32) {
    int nz = 0;
    for (int i = 1; i < 128; i += 2) nz |= u32[i];
    g_idx_is64 = (nz == 0) ? 1 : 0;
}

// ---------------- gather + L2 normalize + align dot (+bf16 store) ------------
__global__ void gather_norm_kernel(const void* __restrict__ u_raw,
                                   const void* __restrict__ v_raw,
                                   const float* __restrict__ emb) {
    int i = blockIdx.x;
    int t = threadIdx.x;

    long long ui, vi;
    if (g_idx_is64) {
        ui = ((const long long*)u_raw)[i];
        vi = ((const long long*)v_raw)[i];
    } else {
        ui = ((const int*)u_raw)[i];
        vi = ((const int*)v_raw)[i];
    }

    float xu = emb[ui * DIM + t];
    float xv = emb[vi * DIM + t];

    __shared__ float red[8];
    float su2 = xu * xu, sv2 = xv * xv;
    #pragma unroll
    for (int off = 16; off; off >>= 1) {
        su2 += __shfl_down_sync(0xffffffffu, su2, off);
        sv2 += __shfl_down_sync(0xffffffffu, sv2, off);
    }
    int w = t >> 5;
    if ((t & 31) == 0) { red[w] = su2; red[4 + w] = sv2; }
    __syncthreads();
    float ssu = red[0] + red[1] + red[2] + red[3];
    float ssv = red[4] + red[5] + red[6] + red[7];

    float du = fmaxf(sqrtf(ssu), 1e-12f);
    float dv = fmaxf(sqrtf(ssv), 1e-12f);
    float su = xu / du;
    float sv = xv / dv;

    g_src[i * DIM + t] = __float2bfloat16(su);
    g_pos[i * DIM + t] = __float2bfloat16(sv);

    float dp = su * sv;
    #pragma unroll
    for (int off = 16; off; off >>= 1)
        dp += __shfl_down_sync(0xffffffffu, dp, off);
    __syncthreads();
    if ((t & 31) == 0) red[w] = dp;
    __syncthreads();
    if (t == 0) g_dot[i] = red[0] + red[1] + red[2] + red[3];
}

// ---------------- fused HMMA Gram (symmetric half) + exp sums ----------------
// grid (64, 2, 2): x = row-block bi, y = matrix, z = t-range half.
// Tournament: tiles (bi, (bi+t)%64) for t in z's half of [0,NT), NT=32(+1 bi<32).
// 2 CTAs/SM; k-loop restructured so live regs < 128 (no spill at (256,2)).
#define SM_A  0
#define SM_B0 TILE_BYTES
#define SM_B1 (2 * TILE_BYTES)
#define SM_TOTAL (3 * TILE_BYTES)

__device__ __forceinline__ void load_tile(uint32_t sdst, const uint4* eg,
                                          int row0, int tid) {
    #pragma unroll
    for (int it = 0; it < 8; it++) {
        int idx = tid + it * 256;
        int r = idx >> 4, c = idx & 15;
        CP_ASYNC16(sdst + r * SSTRIDE + c * 16, eg + (row0 + r) * 16 + c);
    }
}

__global__ void __launch_bounds__(256, 2) lse_kernel() {
    extern __shared__ char smem[];
    const uint32_t sbase = smem_u32(smem);
    const int tid = threadIdx.x;
    const int lane = tid & 31;
    const int warp_m = (tid >> 5) >> 2;   // 0..1 -> 64 rows each
    const int warp_n = (tid >> 5) & 3;    // 0..3 -> 32 cols each
    const int m_base = warp_m * 64;
    const int n_base = warp_n * 32;
    const int bi = blockIdx.x;
    const int my = blockIdx.y;
    const int zz = blockIdx.z;
    const int NT = 32 + (bi < 32 ? 1 : 0);
    const int t0 = zz * 16;
    const int tEnd = zz == 0 ? 16 : NT;

    const __nv_bfloat16* e = (my == 0) ? g_src : g_pos;
    const uint4* eg = (const uint4*)e;

    // prologue: A + B(t0) in group0, B(t0+1) in group1
    load_tile(sbase + SM_A, eg, bi * 128, tid);
    load_tile(sbase + SM_B0, eg, ((bi + t0) & 63) * 128, tid);
    CP_COMMIT();
    load_tile(sbase + SM_B1, eg, ((bi + t0 + 1) & 63) * 128, tid);
    CP_COMMIT();

    const int l15 = lane & 15;
    const uint32_t aAddr0 = sbase + SM_A +
        (uint32_t)(m_base + l15) * SSTRIDE + (uint32_t)(lane >> 4) * 16;
    const uint32_t bOff0 =
        (uint32_t)(n_base + (l15 & 7)) * SSTRIDE + (uint32_t)(l15 >> 3) * 16;

    float acc[4][4][4];
    #pragma unroll
    for (int mt = 0; mt < 4; mt++)
        #pragma unroll
        for (int nt = 0; nt < 4; nt++)
            #pragma unroll
            for (int q = 0; q < 4; q++) acc[mt][nt][q] = 0.f;

    float rowsum[8];
    #pragma unroll
    for (int j = 0; j < 8; j++) rowsum[j] = 0.f;

    const float CEX = 2.0f * 1.4426950408889634f;   // exp(2d-2) = 2^(CEX*d - CEX)

    for (int t = t0; t < tEnd; t++) {
        if (t < tEnd - 1) { CP_WAIT1(); } else { CP_WAIT0(); }
        __syncthreads();

        const uint32_t bAddr0 = sbase + ((t & 1) ? SM_B1 : SM_B0) + bOff0;

        #pragma unroll
        for (int k = 0; k < 8; k++) {
            uint32_t b[4][2];
            #pragma unroll
            for (int nt = 0; nt < 4; nt++)
                LDMATRIX_X2(b[nt][0], b[nt][1],
                            bAddr0 + nt * (8 * SSTRIDE) + k * 32);
            #pragma unroll
            for (int mt = 0; mt < 4; mt++) {
                uint32_t a0, a1, a2, a3;
                LDMATRIX_X4(a0, a1, a2, a3,
                            aAddr0 + mt * (16 * SSTRIDE) + k * 32);
                #pragma unroll
                for (int nt = 0; nt < 4; nt++)
                    MMA16816(acc[mt][nt][0], acc[mt][nt][1],
                             acc[mt][nt][2], acc[mt][nt][3],
                             a0, a1, a2, a3, b[nt][0], b[nt][1]);
            }
        }

        __syncthreads();            // all warps done reading this B buffer
        if (t + 2 < tEnd) {
            load_tile(sbase + ((t & 1) ? SM_B1 : SM_B0), eg,
                      ((bi + t + 2) & 63) * 128, tid);
            CP_COMMIT();
        }

        // epilogue: ev = exp(2d-2); row sums always, col sums for t>0
        float cs[4][2];
        #pragma unroll
        for (int nt = 0; nt < 4; nt++) { cs[nt][0] = 0.f; cs[nt][1] = 0.f; }

        #pragma unroll
        for (int mt = 0; mt < 4; mt++) {
            float s0 = 0.f, s1 = 0.f;
            #pragma unroll
            for (int nt = 0; nt < 4; nt++) {
                float e0 = ex2_approx(fmaf(CEX, acc[mt][nt][0], -CEX));
                float e1 = ex2_approx(fmaf(CEX, acc[mt][nt][1], -CEX));
                float e2 = ex2_approx(fmaf(CEX, acc[mt][nt][2], -CEX));
                float e3 = ex2_approx(fmaf(CEX, acc[mt][nt][3], -CEX));
                s0 += e0 + e1;
                s1 += e2 + e3;
                cs[nt][0] += e0 + e2;
                cs[nt][1] += e1 + e3;
                acc[mt][nt][0] = 0.f; acc[mt][nt][1] = 0.f;
                acc[mt][nt][2] = 0.f; acc[mt][nt][3] = 0.f;
            }
            rowsum[mt * 2]     += s0;
            rowsum[mt * 2 + 1] += s1;
        }

        if (t != 0) {
            // reduce col partials over the 8 row-groups within this warp,
            // then lanes 0-3 write this warp's 32 columns straight to gmem.
            #pragma unroll
            for (int nt = 0; nt < 4; nt++) {
                #pragma unroll
                for (int j = 0; j < 2; j++) {
                    cs[nt][j] += __shfl_xor_sync(0xffffffffu, cs[nt][j], 4);
                    cs[nt][j] += __shfl_xor_sync(0xffffffffu, cs[nt][j], 8);
                    cs[nt][j] += __shfl_xor_sync(0xffffffffu, cs[nt][j], 16);
                }
            }
            if (lane < 4) {
                int bj = (bi + t) & 63;
                float2* dst = (float2*)&g_cross[
                    ((((my * 64 + bj) * 33 + t) * 2 + warp_m) * 128)
                    + n_base + lane * 2];
                #pragma unroll
                for (int nt = 0; nt < 4; nt++)
                    dst[nt * 4] = make_float2(cs[nt][0], cs[nt][1]);
            }
        }
    }

    // ---- own row sums: quad lanes share rows ----
    #pragma unroll
    for (int j = 0; j < 8; j++) {
        rowsum[j] += __shfl_xor_sync(0xffffffffu, rowsum[j], 1);
        rowsum[j] += __shfl_xor_sync(0xffffffffu, rowsum[j], 2);
    }

    float* red = (float*)smem;            // reuse A region
    __syncthreads();
    if ((lane & 3) == 0) {
        #pragma unroll
        for (int mt = 0; mt < 4; mt++) {
            int row = m_base + mt * 16 + (lane >> 2);
            red[warp_n * 128 + row]     = rowsum[mt * 2];
            red[warp_n * 128 + row + 8] = rowsum[mt * 2 + 1];
        }
    }
    __syncthreads();
    if (tid < 128) {
        float s = red[tid] + red[128 + tid] + red[256 + tid] + red[384 + tid];
        g_rowsum[((my * 2 + zz) * 64 + bi) * 128 + tid] = s;
    }
}

// ---------------- per-row combine + log + block partial (+dot partial) -------
__global__ void reduce_kernel() {
    const int bi = blockIdx.x;
    const int my = blockIdx.y;
    const int tid = threadIdx.x;         // 0..255
    const int r = tid & 127;
    const int h = tid >> 7;

    const float* cr = &g_cross[(my * 64 + bi) * 33 * 2 * 128 + r];
    const int tMax = (bi >= 32) ? 32 : 31;
    float s = 0.f;
    if (h == 0) {
        s += g_rowsum[((my * 2 + 0) * 64 + bi) * 128 + r];
        s += g_rowsum[((my * 2 + 1) * 64 + bi) * 128 + r];
        #pragma unroll 4
        for (int t = 1; t <= 16; t++) s += cr[t * 256] + cr[t * 256 + 128];
    } else {
        for (int t = 17; t <= tMax; t++) s += cr[t * 256] + cr[t * 256 + 128];
    }

    __shared__ float sm2[256];
    sm2[tid] = s;
    __syncthreads();
    if (h == 0) sm2[r] = logf(sm2[r] + sm2[r + 128]);
    __syncthreads();
    for (int st = 64; st; st >>= 1) {
        if (tid < st) sm2[tid] += sm2[tid + st];
        __syncthreads();
    }
    if (tid == 0) g_lse_partial[my * 64 + bi] = sm2[0];

    if (my == 0) {
        sm2[tid] = (tid < 128) ? g_dot[bi * 128 + tid] : 0.f;
        __syncthreads();
        for (int st = 128; st; st >>= 1) {
            if (tid < st) sm2[tid] += sm2[tid + st];
            __syncthreads();
        }
        if (tid == 0) g_dotp[bi] = sm2[0];
    }
}

// ---------------- finalize ----------------------------------------------------
__global__ void finalize_kernel(float* __restrict__ out) {
    int tid = threadIdx.x;               // 128 threads
    float l = g_lse_partial[tid];
    float a = (tid < 64) ? g_dotp[tid] : 0.f;
    __shared__ float ra[128], rl[128];
    ra[tid] = a; rl[tid] = l;
    __syncthreads();
    for (int s = 64; s; s >>= 1) {
        if (tid < s) { ra[tid] += ra[tid + s]; rl[tid] += rl[tid + s]; }
        __syncthreads();
    }
    if (tid == 0) {
        float align_mean = ra[0] / (float)NPTS;
        float align = 2.0f - 2.0f * align_mean;
        float unif  = rl[0] / (float)NPTS;
        out[0] = 4.0f * align + 2.0f * unif;
    }
}

// ---------------- launch ------------------------------------------------------
extern "C" void kernel_launch(void* const* d_in, const int* in_sizes, int n_in,
                              void* d_out, int out_size) {
    const void*  u   = d_in[0];
    const void*  v   = d_in[1];
    const float* emb = (const float*)d_in[2];

    cudaFuncSetAttribute(lse_kernel,
                         cudaFuncAttributeMaxDynamicSharedMemorySize, SM_TOTAL);

    sniff_kernel<<<1, 1>>>((const int*)u);
    gather_norm_kernel<<<NPTS, DIM>>>(u, v, emb);
    lse_kernel<<<dim3(64, 2, 2), 256, SM_TOTAL>>>();
    reduce_kernel<<<dim3(64, 2), 256>>>();
    finalize_kernel<<<1, 128>>>((float*)d_out);
}

// round 10
// speedup vs baseline: 1.8877x; 1.0123x over previous
#include <cuda_runtime.h>
#include <cuda_fp16.h>
#include <cstdint>

#define NPTS 8192
#define DIM 128
#define SSTRIDE 272                   // f16 tile row stride bytes (136 halves)
#define TILE_BYTES (128 * SSTRIDE)    // 34816

// ---------------- scratch (device globals; no allocations allowed) ----------
__device__ __half g_src[NPTS * DIM];
__device__ __half g_pos[NPTS * DIM];
__device__ float g_dot[NPTS];
__device__ float g_rowsum[2 * 2 * NPTS];            // [my][z][bi][row]
__device__ float g_cross[2 * 64 * 33 * 2 * 128];    // [my][bj][t][warp_m][row]
__device__ float g_lse_partial[128];                // [my(2)][row-block(64)]
__device__ float g_dotp[64];
__device__ int   g_idx_is64;

// ---------------- PTX helpers ------------------------------------------------
__device__ __forceinline__ uint32_t smem_u32(const void* p) {
    uint32_t a;
    asm("{ .reg .u64 t; cvta.to.shared.u64 t, %1; cvt.u32.u64 %0, t; }"
        : "=r"(a) : "l"(p));
    return a;
}

__device__ __forceinline__ float ex2_approx(float x) {
    float y;
    asm("ex2.approx.f32 %0, %1;" : "=f"(y) : "f"(x));
    return y;
}

#define CP_ASYNC16(dst, src) \
    asm volatile("cp.async.cg.shared.global [%0], [%1], 16;" :: "r"(dst), "l"(src) : "memory")
#define CP_COMMIT() asm volatile("cp.async.commit_group;" ::: "memory")
#define CP_WAIT1()  asm volatile("cp.async.wait_group 1;" ::: "memory")
#define CP_WAIT0()  asm volatile("cp.async.wait_group 0;" ::: "memory")

#define LDMATRIX_X4(r0, r1, r2, r3, addr) \
    asm volatile("ldmatrix.sync.aligned.m8n8.x4.shared.b16 {%0,%1,%2,%3}, [%4];" \
                 : "=r"(r0), "=r"(r1), "=r"(r2), "=r"(r3) : "r"(addr))
#define LDMATRIX_X2(r0, r1, addr) \
    asm volatile("ldmatrix.sync.aligned.m8n8.x2.shared.b16 {%0,%1}, [%2];" \
                 : "=r"(r0), "=r"(r1) : "r"(addr))

// f16 x f16 -> f16 accumulate: D/C are 2 x .f16x2 registers.
#define MMA16816H(c0, c1, a0, a1, a2, a3, b0, b1) \
    asm volatile("mma.sync.aligned.m16n8k16.row.col.f16.f16.f16.f16 " \
                 "{%0,%1}, {%2,%3,%4,%5}, {%6,%7}, {%0,%1};" \
                 : "+r"(c0), "+r"(c1) \
                 : "r"(a0), "r"(a1), "r"(a2), "r"(a3), "r"(b0), "r"(b1))

// ---------------- dtype sniff: int64 vs int32 indices ------------------------
__global__ void sniff_kernel(const int* __restrict__ u32) {
    int nz = 0;
    for (int i = 1; i < 128; i += 2) nz |= u32[i];
    g_idx_is64 = (nz == 0) ? 1 : 0;
}

// ---------------- gather + L2 normalize + align dot (+f16 store) -------------
__global__ void gather_norm_kernel(const void* __restrict__ u_raw,
                                   const void* __restrict__ v_raw,
                                   const float* __restrict__ emb) {
    int i = blockIdx.x;
    int t = threadIdx.x;

    long long ui, vi;
    if (g_idx_is64) {
        ui = ((const long long*)u_raw)[i];
        vi = ((const long long*)v_raw)[i];
    } else {
        ui = ((const int*)u_raw)[i];
        vi = ((const int*)v_raw)[i];
    }

    float xu = emb[ui * DIM + t];
    float xv = emb[vi * DIM + t];

    __shared__ float red[8];
    float su2 = xu * xu, sv2 = xv * xv;
    #pragma unroll
    for (int off = 16; off; off >>= 1) {
        su2 += __shfl_down_sync(0xffffffffu, su2, off);
        sv2 += __shfl_down_sync(0xffffffffu, sv2, off);
    }
    int w = t >> 5;
    if ((t & 31) == 0) { red[w] = su2; red[4 + w] = sv2; }
    __syncthreads();
    float ssu = red[0] + red[1] + red[2] + red[3];
    float ssv = red[4] + red[5] + red[6] + red[7];

    float du = fmaxf(sqrtf(ssu), 1e-12f);
    float dv = fmaxf(sqrtf(ssv), 1e-12f);
    float su = xu / du;
    float sv = xv / dv;

    g_src[i * DIM + t] = __float2half_rn(su);
    g_pos[i * DIM + t] = __float2half_rn(sv);

    float dp = su * sv;
    #pragma unroll
    for (int off = 16; off; off >>= 1)
        dp += __shfl_down_sync(0xffffffffu, dp, off);
    __syncthreads();
    if ((t & 31) == 0) red[w] = dp;
    __syncthreads();
    if (t == 0) g_dot[i] = red[0] + red[1] + red[2] + red[3];
}

// ---------------- fused HMMA-f16 Gram (symmetric half) + exp sums ------------
// grid (64, 2, 2): x = row-block bi, y = matrix, z = t-range half.
// Tournament: tiles (bi, (bi+t)%64) for t in z's half of [0,NT), NT=32(+1 bi<32).
// f16 accumulators (2 regs/fragment) -> ~90 live regs -> true 2 CTAs/SM.
#define SM_A  0
#define SM_B0 TILE_BYTES
#define SM_B1 (2 * TILE_BYTES)
#define SM_TOTAL (3 * TILE_BYTES)

__device__ __forceinline__ void load_tile(uint32_t sdst, const uint4* eg,
                                          int row0, int tid) {
    #pragma unroll
    for (int it = 0; it < 8; it++) {
        int idx = tid + it * 256;
        int r = idx >> 4, c = idx & 15;
        CP_ASYNC16(sdst + r * SSTRIDE + c * 16, eg + (row0 + r) * 16 + c);
    }
}

__global__ void __launch_bounds__(256, 2) lse_kernel() {
    extern __shared__ char smem[];
    const uint32_t sbase = smem_u32(smem);
    const int tid = threadIdx.x;
    const int lane = tid & 31;
    const int warp_m = (tid >> 5) >> 2;   // 0..1 -> 64 rows each
    const int warp_n = (tid >> 5) & 3;    // 0..3 -> 32 cols each
    const int m_base = warp_m * 64;
    const int n_base = warp_n * 32;
    const int bi = blockIdx.x;
    const int my = blockIdx.y;
    const int zz = blockIdx.z;
    const int NT = 32 + (bi < 32 ? 1 : 0);
    const int t0 = zz * 16;
    const int tEnd = zz == 0 ? 16 : NT;

    const __half* e = (my == 0) ? g_src : g_pos;
    const uint4* eg = (const uint4*)e;

    // prologue: A + B(t0) in group0, B(t0+1) in group1
    load_tile(sbase + SM_A, eg, bi * 128, tid);
    load_tile(sbase + SM_B0, eg, ((bi + t0) & 63) * 128, tid);
    CP_COMMIT();
    load_tile(sbase + SM_B1, eg, ((bi + t0 + 1) & 63) * 128, tid);
    CP_COMMIT();

    const int l15 = lane & 15;
    const uint32_t aAddr0 = sbase + SM_A +
        (uint32_t)(m_base + l15) * SSTRIDE + (uint32_t)(lane >> 4) * 16;
    const uint32_t bOff0 =
        (uint32_t)(n_base + (l15 & 7)) * SSTRIDE + (uint32_t)(l15 >> 3) * 16;

    uint32_t acc[4][4][2];                // f16x2 accumulators
    #pragma unroll
    for (int mt = 0; mt < 4; mt++)
        #pragma unroll
        for (int nt = 0; nt < 4; nt++) { acc[mt][nt][0] = 0u; acc[mt][nt][1] = 0u; }

    float rowsum[8];
    #pragma unroll
    for (int j = 0; j < 8; j++) rowsum[j] = 0.f;

    const float CEX = 2.0f * 1.4426950408889634f;   // exp(2d-2) = 2^(CEX*d - CEX)

    for (int t = t0; t < tEnd; t++) {
        if (t < tEnd - 1) { CP_WAIT1(); } else { CP_WAIT0(); }
        __syncthreads();

        const uint32_t bAddr0 = sbase + ((t & 1) ? SM_B1 : SM_B0) + bOff0;

        #pragma unroll
        for (int k = 0; k < 8; k++) {
            uint32_t b[4][2];
            #pragma unroll
            for (int nt = 0; nt < 4; nt++)
                LDMATRIX_X2(b[nt][0], b[nt][1],
                            bAddr0 + nt * (8 * SSTRIDE) + k * 32);
            #pragma unroll
            for (int mt = 0; mt < 4; mt++) {
                uint32_t a0, a1, a2, a3;
                LDMATRIX_X4(a0, a1, a2, a3,
                            aAddr0 + mt * (16 * SSTRIDE) + k * 32);
                #pragma unroll
                for (int nt = 0; nt < 4; nt++)
                    MMA16816H(acc[mt][nt][0], acc[mt][nt][1],
                              a0, a1, a2, a3, b[nt][0], b[nt][1]);
            }
        }

        __syncthreads();            // all warps done reading this B buffer
        if (t + 2 < tEnd) {
            load_tile(sbase + ((t & 1) ? SM_B1 : SM_B0), eg,
                      ((bi + t + 2) & 63) * 128, tid);
            CP_COMMIT();
        }

        // epilogue: ev = exp(2d-2); row sums always, col sums for t>0
        float cs[4][2];
        #pragma unroll
        for (int nt = 0; nt < 4; nt++) { cs[nt][0] = 0.f; cs[nt][1] = 0.f; }

        #pragma unroll
        for (int mt = 0; mt < 4; mt++) {
            float s0 = 0.f, s1 = 0.f;
            #pragma unroll
            for (int nt = 0; nt < 4; nt++) {
                float2 f01 = __half22float2(*(__half2*)&acc[mt][nt][0]); // (r,c),(r,c+1)
                float2 f23 = __half22float2(*(__half2*)&acc[mt][nt][1]); // (r+8,c),(r+8,c+1)
                float e0 = ex2_approx(fmaf(CEX, f01.x, -CEX));
                float e1 = ex2_approx(fmaf(CEX, f01.y, -CEX));
                float e2 = ex2_approx(fmaf(CEX, f23.x, -CEX));
                float e3 = ex2_approx(fmaf(CEX, f23.y, -CEX));
                s0 += e0 + e1;
                s1 += e2 + e3;
                cs[nt][0] += e0 + e2;
                cs[nt][1] += e1 + e3;
                acc[mt][nt][0] = 0u; acc[mt][nt][1] = 0u;
            }
            rowsum[mt * 2]     += s0;
            rowsum[mt * 2 + 1] += s1;
        }

        if (t != 0) {
            // reduce col partials over the 8 row-groups within this warp,
            // then lanes 0-3 write this warp's 32 columns straight to gmem.
            #pragma unroll
            for (int nt = 0; nt < 4; nt++) {
                #pragma unroll
                for (int j = 0; j < 2; j++) {
                    cs[nt][j] += __shfl_xor_sync(0xffffffffu, cs[nt][j], 4);
                    cs[nt][j] += __shfl_xor_sync(0xffffffffu, cs[nt][j], 8);
                    cs[nt][j] += __shfl_xor_sync(0xffffffffu, cs[nt][j], 16);
                }
            }
            if (lane < 4) {
                int bj = (bi + t) & 63;
                float2* dst = (float2*)&g_cross[
                    ((((my * 64 + bj) * 33 + t) * 2 + warp_m) * 128)
                    + n_base + lane * 2];
                #pragma unroll
                for (int nt = 0; nt < 4; nt++)
                    dst[nt * 4] = make_float2(cs[nt][0], cs[nt][1]);
            }
        }
    }

    // ---- own row sums: quad lanes share rows ----
    #pragma unroll
    for (int j = 0; j < 8; j++) {
        rowsum[j] += __shfl_xor_sync(0xffffffffu, rowsum[j], 1);
        rowsum[j] += __shfl_xor_sync(0xffffffffu, rowsum[j], 2);
    }

    float* red = (float*)smem;            // reuse A region
    __syncthreads();
    if ((lane & 3) == 0) {
        #pragma unroll
        for (int mt = 0; mt < 4; mt++) {
            int row = m_base + mt * 16 + (lane >> 2);
            red[warp_n * 128 + row]     = rowsum[mt * 2];
            red[warp_n * 128 + row + 8] = rowsum[mt * 2 + 1];
        }
    }
    __syncthreads();
    if (tid < 128) {
        float s = red[tid] + red[128 + tid] + red[256 + tid] + red[384 + tid];
        g_rowsum[((my * 2 + zz) * 64 + bi) * 128 + tid] = s;
    }
}

// ---------------- per-row combine + log + block partial (+dot partial) -------
__global__ void reduce_kernel() {
    const int bi = blockIdx.x;
    const int my = blockIdx.y;
    const int tid = threadIdx.x;         // 0..511
    const int r = tid & 127;
    const int q = tid >> 7;              // quarter 0..3

    const float* cr = &g_cross[(my * 64 + bi) * 33 * 2 * 128 + r];
    const int tMax = (bi >= 32) ? 32 : 31;
    float s = 0.f;
    if (q == 0) {
        s += g_rowsum[((my * 2 + 0) * 64 + bi) * 128 + r];
        s += g_rowsum[((my * 2 + 1) * 64 + bi) * 128 + r];
        #pragma unroll 4
        for (int t = 1; t <= 8; t++)  s += cr[t * 256] + cr[t * 256 + 128];
    } else if (q == 1) {
        #pragma unroll 4
        for (int t = 9; t <= 16; t++) s += cr[t * 256] + cr[t * 256 + 128];
    } else if (q == 2) {
        #pragma unroll 4
        for (int t = 17; t <= 24; t++) s += cr[t * 256] + cr[t * 256 + 128];
    } else {
        for (int t = 25; t <= tMax; t++) s += cr[t * 256] + cr[t * 256 + 128];
    }

    __shared__ float sm2[512];
    sm2[tid] = s;
    __syncthreads();
    if (q == 0)
        sm2[r] = logf(sm2[r] + sm2[r + 128] + sm2[r + 256] + sm2[r + 384]);
    __syncthreads();
    for (int st = 64; st; st >>= 1) {
        if (tid < st) sm2[tid] += sm2[tid + st];
        __syncthreads();
    }
    if (tid == 0) g_lse_partial[my * 64 + bi] = sm2[0];

    if (my == 0) {
        sm2[tid] = (tid < 128) ? g_dot[bi * 128 + tid] : 0.f;
        __syncthreads();
        for (int st = 64; st; st >>= 1) {
            if (tid < st) sm2[tid] += sm2[tid + st];
            __syncthreads();
        }
        if (tid == 0) g_dotp[bi] = sm2[0] + sm2[64];   // careful: 128 values
    }
}

// ---------------- finalize ----------------------------------------------------
__global__ void finalize_kernel(float* __restrict__ out) {
    int tid = threadIdx.x;               // 128 threads
    float l = g_lse_partial[tid];
    float a = (tid < 64) ? g_dotp[tid] : 0.f;
    __shared__ float ra[128], rl[128];
    ra[tid] = a; rl[tid] = l;
    __syncthreads();
    for (int s = 64; s; s >>= 1) {
        if (tid < s) { ra[tid] += ra[tid + s]; rl[tid] += rl[tid + s]; }
        __syncthreads();
    }
    if (tid == 0) {
        float align_mean = ra[0] / (float)NPTS;
        float align = 2.0f - 2.0f * align_mean;
        float unif  = rl[0] / (float)NPTS;
        out[0] = 4.0f * align + 2.0f * unif;
    }
}

// ---------------- launch ------------------------------------------------------
extern "C" void kernel_launch(void* const* d_in, const int* in_sizes, int n_in,
                              void* d_out, int out_size) {
    const void*  u   = d_in[0];
    const void*  v   = d_in[1];
    const float* emb = (const float*)d_in[2];

    cudaFuncSetAttribute(lse_kernel,
                         cudaFuncAttributeMaxDynamicSharedMemorySize, SM_TOTAL);

    sniff_kernel<<<1, 1>>>((const int*)u);
    gather_norm_kernel<<<NPTS, DIM>>>(u, v, emb);
    lse_kernel<<<dim3(64, 2, 2), 256, SM_TOTAL>>>();
    reduce_kernel<<<dim3(64, 2), 512>>>();
    finalize_kernel<<<1, 128>>>((float*)d_out);
}

// round 12
// speedup vs baseline: 1.9621x; 1.0394x over previous
#include <cuda_runtime.h>
#include <cuda_fp16.h>
#include <cstdint>

#define NPTS 8192
#define DIM 128
#define SSTRIDE 272                   // f16 tile row stride bytes (136 halves)
#define TILE_BYTES (128 * SSTRIDE)    // 34816

// ---------------- scratch (device globals; no allocations allowed) ----------
__device__ __half g_src[NPTS * DIM];
__device__ __half g_pos[NPTS * DIM];
__device__ float g_dot[NPTS];
__device__ float g_rowsum[2 * 2 * NPTS];            // [my][z][bi][row]
__device__ float g_cross[2 * 64 * 33 * 2 * 128];    // [my][bj][t][warp_m][row]
__device__ float g_lse_partial[128];                // [my(2)][row-block(64)]
__device__ float g_dotp[64];
__device__ int   g_count;                           // last-block election counter

// ---------------- PTX helpers ------------------------------------------------
__device__ __forceinline__ uint32_t smem_u32(const void* p) {
    uint32_t a;
    asm("{ .reg .u64 t; cvta.to.shared.u64 t, %1; cvt.u32.u64 %0, t; }"
        : "=r"(a) : "l"(p));
    return a;
}

__device__ __forceinline__ float ex2_approx(float x) {
    float y;
    asm("ex2.approx.f32 %0, %1;" : "=f"(y) : "f"(x));
    return y;
}

#define CP_ASYNC16(dst, src) \
    asm volatile("cp.async.cg.shared.global [%0], [%1], 16;" :: "r"(dst), "l"(src) : "memory")
#define CP_COMMIT() asm volatile("cp.async.commit_group;" ::: "memory")
#define CP_WAIT1()  asm volatile("cp.async.wait_group 1;" ::: "memory")
#define CP_WAIT0()  asm volatile("cp.async.wait_group 0;" ::: "memory")

#define LDMATRIX_X4(r0, r1, r2, r3, addr) \
    asm volatile("ldmatrix.sync.aligned.m8n8.x4.shared.b16 {%0,%1,%2,%3}, [%4];" \
                 : "=r"(r0), "=r"(r1), "=r"(r2), "=r"(r3) : "r"(addr))
#define LDMATRIX_X2(r0, r1, addr) \
    asm volatile("ldmatrix.sync.aligned.m8n8.x2.shared.b16 {%0,%1}, [%2];" \
                 : "=r"(r0), "=r"(r1) : "r"(addr))

// f16 x f16 -> f16 accumulate: D/C are 2 x .f16x2 registers.
#define MMA16816H(c0, c1, a0, a1, a2, a3, b0, b1) \
    asm volatile("mma.sync.aligned.m16n8k16.row.col.f16.f16.f16.f16 " \
                 "{%0,%1}, {%2,%3,%4,%5}, {%6,%7}, {%0,%1};" \
                 : "+r"(c0), "+r"(c1) \
                 : "r"(a0), "r"(a1), "r"(a2), "r"(a3), "r"(b0), "r"(b1))

// ---------------- gather + L2 normalize + align dot (+f16 store) -------------
// grid 256 x block 256. Warp-per-row, 4 rows per warp. Lane l owns dims
// [4l, 4l+4). int64-vs-int32 index detection done per-warp (odd 32-bit lanes
// of an int64 array of values < 2^31 are all zero).
__global__ void __launch_bounds__(256) gather_norm_kernel(
        const void* __restrict__ u_raw, const void* __restrict__ v_raw,
        const float* __restrict__ emb) {
    const int lane = threadIdx.x & 31;
    const int warp = threadIdx.x >> 5;

    const int* u32 = (const int*)u_raw;
    int nz = u32[2 * lane + 1];
    #pragma unroll
    for (int off = 16; off; off >>= 1)
        nz |= __shfl_xor_sync(0xffffffffu, nz, off);
    const bool is64 = (nz == 0);

    #pragma unroll
    for (int it = 0; it < 4; it++) {
        int row = (blockIdx.x * 4 + it) * 8 + warp;

        long long ui, vi;
        if (is64) {
            ui = ((const long long*)u_raw)[row];
            vi = ((const long long*)v_raw)[row];
        } else {
            ui = ((const int*)u_raw)[row];
            vi = ((const int*)v_raw)[row];
        }

        float4 xu = ((const float4*)(emb + ui * DIM))[lane];
        float4 xv = ((const float4*)(emb + vi * DIM))[lane];

        float su2 = xu.x * xu.x + xu.y * xu.y + xu.z * xu.z + xu.w * xu.w;
        float sv2 = xv.x * xv.x + xv.y * xv.y + xv.z * xv.z + xv.w * xv.w;
        #pragma unroll
        for (int off = 16; off; off >>= 1) {
            su2 += __shfl_xor_sync(0xffffffffu, su2, off);
            sv2 += __shfl_xor_sync(0xffffffffu, sv2, off);
        }

        float ru = 1.0f / fmaxf(sqrtf(su2), 1e-12f);
        float rv = 1.0f / fmaxf(sqrtf(sv2), 1e-12f);
        float sux = xu.x * ru, suy = xu.y * ru, suz = xu.z * ru, suw = xu.w * ru;
        float svx = xv.x * rv, svy = xv.y * rv, svz = xv.z * rv, svw = xv.w * rv;

        __half2 u01 = __floats2half2_rn(sux, suy);
        __half2 u23 = __floats2half2_rn(suz, suw);
        __half2 v01 = __floats2half2_rn(svx, svy);
        __half2 v23 = __floats2half2_rn(svz, svw);
        *(uint2*)&g_src[row * DIM + lane * 4] =
            make_uint2(*(uint32_t*)&u01, *(uint32_t*)&u23);
        *(uint2*)&g_pos[row * DIM + lane * 4] =
            make_uint2(*(uint32_t*)&v01, *(uint32_t*)&v23);

        float dp = sux * svx + suy * svy + suz * svz + suw * svw;
        #pragma unroll
        for (int off = 16; off; off >>= 1)
            dp += __shfl_xor_sync(0xffffffffu, dp, off);
        if (lane == 0) g_dot[row] = dp;
    }
}

// ---------------- fused HMMA-f16 Gram (symmetric half) + exp sums ------------
// grid (64, 2, 2): x = row-block bi, y = matrix, z = t-range half.
// Tournament: tiles (bi, (bi+t)%64) for t in z's half of [0,NT), NT=32(+1 bi<32).
#define SM_A  0
#define SM_B0 TILE_BYTES
#define SM_B1 (2 * TILE_BYTES)
#define SM_TOTAL (3 * TILE_BYTES)

__device__ __forceinline__ void load_tile(uint32_t sdst, const uint4* eg,
                                          int row0, int tid) {
    #pragma unroll
    for (int it = 0; it < 8; it++) {
        int idx = tid + it * 256;
        int r = idx >> 4, c = idx & 15;
        CP_ASYNC16(sdst + r * SSTRIDE + c * 16, eg + (row0 + r) * 16 + c);
    }
}

__global__ void __launch_bounds__(256, 2) lse_kernel() {
    extern __shared__ char smem[];
    const uint32_t sbase = smem_u32(smem);
    const int tid = threadIdx.x;
    const int lane = tid & 31;
    const int warp_m = (tid >> 5) >> 2;   // 0..1 -> 64 rows each
    const int warp_n = (tid >> 5) & 3;    // 0..3 -> 32 cols each
    const int m_base = warp_m * 64;
    const int n_base = warp_n * 32;
    const int bi = blockIdx.x;
    const int my = blockIdx.y;
    const int zz = blockIdx.z;
    const int NT = 32 + (bi < 32 ? 1 : 0);
    const int t0 = zz * 16;
    const int tEnd = zz == 0 ? 16 : NT;

    const __half* e = (my == 0) ? g_src : g_pos;
    const uint4* eg = (const uint4*)e;

    // prologue: A + B(t0) in group0, B(t0+1) in group1
    load_tile(sbase + SM_A, eg, bi * 128, tid);
    load_tile(sbase + SM_B0, eg, ((bi + t0) & 63) * 128, tid);
    CP_COMMIT();
    load_tile(sbase + SM_B1, eg, ((bi + t0 + 1) & 63) * 128, tid);
    CP_COMMIT();

    const int l15 = lane & 15;
    const uint32_t aAddr0 = sbase + SM_A +
        (uint32_t)(m_base + l15) * SSTRIDE + (uint32_t)(lane >> 4) * 16;
    const uint32_t bOff0 =
        (uint32_t)(n_base + (l15 & 7)) * SSTRIDE + (uint32_t)(l15 >> 3) * 16;

    uint32_t acc[4][4][2];                // f16x2 accumulators
    #pragma unroll
    for (int mt = 0; mt < 4; mt++)
        #pragma unroll
        for (int nt = 0; nt < 4; nt++) { acc[mt][nt][0] = 0u; acc[mt][nt][1] = 0u; }

    float rowsum[8];
    #pragma unroll
    for (int j = 0; j < 8; j++) rowsum[j] = 0.f;

    const float CEX = 2.0f * 1.4426950408889634f;   // exp(2d-2) = 2^(CEX*d - CEX)

    for (int t = t0; t < tEnd; t++) {
        if (t < tEnd - 1) { CP_WAIT1(); } else { CP_WAIT0(); }
        __syncthreads();

        const uint32_t bAddr0 = sbase + ((t & 1) ? SM_B1 : SM_B0) + bOff0;

        #pragma unroll
        for (int k = 0; k < 8; k++) {
            uint32_t b[4][2];
            #pragma unroll
            for (int nt = 0; nt < 4; nt++)
                LDMATRIX_X2(b[nt][0], b[nt][1],
                            bAddr0 + nt * (8 * SSTRIDE) + k * 32);
            #pragma unroll
            for (int mt = 0; mt < 4; mt++) {
                uint32_t a0, a1, a2, a3;
                LDMATRIX_X4(a0, a1, a2, a3,
                            aAddr0 + mt * (16 * SSTRIDE) + k * 32);
                #pragma unroll
                for (int nt = 0; nt < 4; nt++)
                    MMA16816H(acc[mt][nt][0], acc[mt][nt][1],
                              a0, a1, a2, a3, b[nt][0], b[nt][1]);
            }
        }

        __syncthreads();            // all warps done reading this B buffer
        if (t + 2 < tEnd) {
            load_tile(sbase + ((t & 1) ? SM_B1 : SM_B0), eg,
                      ((bi + t + 2) & 63) * 128, tid);
            CP_COMMIT();
        }

        // epilogue: ev = exp(2d-2); row sums always, col sums for t>0
        float cs[4][2];
        #pragma unroll
        for (int nt = 0; nt < 4; nt++) { cs[nt][0] = 0.f; cs[nt][1] = 0.f; }

        #pragma unroll
        for (int mt = 0; mt < 4; mt++) {
            float s0 = 0.f, s1 = 0.f;
            #pragma unroll
            for (int nt = 0; nt < 4; nt++) {
                float2 f01 = __half22float2(*(__half2*)&acc[mt][nt][0]);
                float2 f23 = __half22float2(*(__half2*)&acc[mt][nt][1]);
                float e0 = ex2_approx(fmaf(CEX, f01.x, -CEX));
                float e1 = ex2_approx(fmaf(CEX, f01.y, -CEX));
                float e2 = ex2_approx(fmaf(CEX, f23.x, -CEX));
                float e3 = ex2_approx(fmaf(CEX, f23.y, -CEX));
                s0 += e0 + e1;
                s1 += e2 + e3;
                cs[nt][0] += e0 + e2;
                cs[nt][1] += e1 + e3;
                acc[mt][nt][0] = 0u; acc[mt][nt][1] = 0u;
            }
            rowsum[mt * 2]     += s0;
            rowsum[mt * 2 + 1] += s1;
        }

        if (t != 0) {
            #pragma unroll
            for (int nt = 0; nt < 4; nt++) {
                #pragma unroll
                for (int j = 0; j < 2; j++) {
                    cs[nt][j] += __shfl_xor_sync(0xffffffffu, cs[nt][j], 4);
                    cs[nt][j] += __shfl_xor_sync(0xffffffffu, cs[nt][j], 8);
                    cs[nt][j] += __shfl_xor_sync(0xffffffffu, cs[nt][j], 16);
                }
            }
            if (lane < 4) {
                int bj = (bi + t) & 63;
                float2* dst = (float2*)&g_cross[
                    ((((my * 64 + bj) * 33 + t) * 2 + warp_m) * 128)
                    + n_base + lane * 2];
                #pragma unroll
                for (int nt = 0; nt < 4; nt++)
                    dst[nt * 4] = make_float2(cs[nt][0], cs[nt][1]);
            }
        }
    }

    // ---- own row sums: quad lanes share rows ----
    #pragma unroll
    for (int j = 0; j < 8; j++) {
        rowsum[j] += __shfl_xor_sync(0xffffffffu, rowsum[j], 1);
        rowsum[j] += __shfl_xor_sync(0xffffffffu, rowsum[j], 2);
    }

    float* red = (float*)smem;            // reuse A region
    __syncthreads();
    if ((lane & 3) == 0) {
        #pragma unroll
        for (int mt = 0; mt < 4; mt++) {
            int row = m_base + mt * 16 + (lane >> 2);
            red[warp_n * 128 + row]     = rowsum[mt * 2];
            red[warp_n * 128 + row + 8] = rowsum[mt * 2 + 1];
        }
    }
    __syncthreads();
    if (tid < 128) {
        float s = red[tid] + red[128 + tid] + red[256 + tid] + red[384 + tid];
        g_rowsum[((my * 2 + zz) * 64 + bi) * 128 + tid] = s;
    }
}

// ------- per-row combine + log + block partial + fenced last-block finalize --
__global__ void reduce_kernel(float* __restrict__ out) {
    const int bi = blockIdx.x;
    const int my = blockIdx.y;
    const int tid = threadIdx.x;         // 0..511
    const int r = tid & 127;
    const int q = tid >> 7;              // quarter 0..3

    const float* cr = &g_cross[(my * 64 + bi) * 33 * 2 * 128 + r];
    const int tMax = (bi >= 32) ? 32 : 31;
    float s = 0.f;
    if (q == 0) {
        s += g_rowsum[((my * 2 + 0) * 64 + bi) * 128 + r];
        s += g_rowsum[((my * 2 + 1) * 64 + bi) * 128 + r];
        #pragma unroll 4
        for (int t = 1; t <= 8; t++)  s += cr[t * 256] + cr[t * 256 + 128];
    } else if (q == 1) {
        #pragma unroll 4
        for (int t = 9; t <= 16; t++) s += cr[t * 256] + cr[t * 256 + 128];
    } else if (q == 2) {
        #pragma unroll 4
        for (int t = 17; t <= 24; t++) s += cr[t * 256] + cr[t * 256 + 128];
    } else {
        for (int t = 25; t <= tMax; t++) s += cr[t * 256] + cr[t * 256 + 128];
    }

    __shared__ float sm2[512];
    sm2[tid] = s;
    __syncthreads();
    if (q == 0)
        sm2[r] = logf(sm2[r] + sm2[r + 128] + sm2[r + 256] + sm2[r + 384]);
    __syncthreads();
    // tree over sm2[0..127]: first step folds [64..127] into [0..63]
    for (int st = 64; st; st >>= 1) {
        if (tid < st) sm2[tid] += sm2[tid + st];
        __syncthreads();
    }
    if (tid == 0) g_lse_partial[my * 64 + bi] = sm2[0];   // sm2[0] = full sum

    if (my == 0) {
        sm2[tid] = (tid < 128) ? g_dot[bi * 128 + tid] : 0.f;
        __syncthreads();
        for (int st = 64; st; st >>= 1) {
            if (tid < st) sm2[tid] += sm2[tid + st];
            __syncthreads();
        }
        if (tid == 0) g_dotp[bi] = sm2[0];                // full 128-sum
    }

    // ---- last-of-128-blocks finalize (threadfence + counter election) ----
    __shared__ int slast;
    __syncthreads();
    if (tid == 0) {
        __threadfence();
        int old = atomicAdd(&g_count, 1);
        slast = ((old & 127) == 127) ? 1 : 0;
    }
    __syncthreads();
    if (slast) {
        __threadfence();
        if (tid < 128) {
            sm2[tid]       = g_lse_partial[tid];
            sm2[256 + tid] = (tid < 64) ? g_dotp[tid] : 0.f;
        }
        __syncthreads();
        for (int st = 64; st; st >>= 1) {
            if (tid < st) {
                sm2[tid]       += sm2[tid + st];
                sm2[256 + tid] += sm2[256 + tid + st];
            }
            __syncthreads();
        }
        if (tid == 0) {
            float lsum = sm2[0];                    // full 128-partial sum
            float asum = sm2[256];                  // full 64-partial sum
            float align_mean = asum / (float)NPTS;
            float align = 2.0f - 2.0f * align_mean;
            float unif  = lsum / (float)NPTS;
            out[0] = 4.0f * align + 2.0f * unif;
        }
    }
}

// ---------------- launch ------------------------------------------------------
extern "C" void kernel_launch(void* const* d_in, const int* in_sizes, int n_in,
                              void* d_out, int out_size) {
    const void*  u   = d_in[0];
    const void*  v   = d_in[1];
    const float* emb = (const float*)d_in[2];

    cudaFuncSetAttribute(lse_kernel,
                         cudaFuncAttributeMaxDynamicSharedMemorySize, SM_TOTAL);

    gather_norm_kernel<<<256, 256>>>(u, v, emb);
    lse_kernel<<<dim3(64, 2, 2), 256, SM_TOTAL>>>();
    reduce_kernel<<<dim3(64, 2), 512>>>((float*)d_out);
}

// round 13
// speedup vs baseline: 2.1346x; 1.0879x over previous
#include <cuda_runtime.h>
#include <cuda_fp16.h>
#include <cstdint>

#define NPTS 8192
#define DIM 128
#define SSTRIDE 272                   // f16 tile row stride bytes (136 halves)
#define TILE_BYTES (128 * SSTRIDE)    // 34816

// ---------------- scratch (device globals; no allocations allowed) ----------
__device__ __half g_src[NPTS * DIM];
__device__ __half g_pos[NPTS * DIM];
__device__ float g_dot[NPTS];
__device__ float g_rowsum[2 * 2 * NPTS];            // [my][z][bi][row]
__device__ float g_cross[2 * 64 * 33 * 2 * 128];    // [my][bj][t][warp_m][row]
__device__ float g_lse_partial[128];                // [my(2)][row-block(64)]
__device__ float g_dotp[64];
__device__ int   g_count;                           // last-block election counter

// ---------------- PTX helpers ------------------------------------------------
__device__ __forceinline__ uint32_t smem_u32(const void* p) {
    uint32_t a;
    asm("{ .reg .u64 t; cvta.to.shared.u64 t, %1; cvt.u32.u64 %0, t; }"
        : "=r"(a) : "l"(p));
    return a;
}

// packed f16x2 helpers: pack two f32 (hi, lo), exp2, add
__device__ __forceinline__ uint32_t packh2(float hi, float lo) {
    uint32_t d;
    asm("cvt.rn.f16x2.f32 %0, %1, %2;" : "=r"(d) : "f"(hi), "f"(lo));
    return d;
}
__device__ __forceinline__ uint32_t ex2h2(uint32_t a) {
    uint32_t d;
    asm("ex2.approx.f16x2 %0, %1;" : "=r"(d) : "r"(a));
    return d;
}
__device__ __forceinline__ uint32_t hadd2u(uint32_t a, uint32_t b) {
    uint32_t d;
    asm("add.f16x2 %0, %1, %2;" : "=r"(d) : "r"(a), "r"(b));
    return d;
}

#define CP_ASYNC16(dst, src) \
    asm volatile("cp.async.cg.shared.global [%0], [%1], 16;" :: "r"(dst), "l"(src) : "memory")
#define CP_COMMIT() asm volatile("cp.async.commit_group;" ::: "memory")
#define CP_WAIT1()  asm volatile("cp.async.wait_group 1;" ::: "memory")
#define CP_WAIT0()  asm volatile("cp.async.wait_group 0;" ::: "memory")

#define LDMATRIX_X4(r0, r1, r2, r3, addr) \
    asm volatile("ldmatrix.sync.aligned.m8n8.x4.shared.b16 {%0,%1,%2,%3}, [%4];" \
                 : "=r"(r0), "=r"(r1), "=r"(r2), "=r"(r3) : "r"(addr))
#define LDMATRIX_X2(r0, r1, addr) \
    asm volatile("ldmatrix.sync.aligned.m8n8.x2.shared.b16 {%0,%1}, [%2];" \
                 : "=r"(r0), "=r"(r1) : "r"(addr))

// f16 x f16 -> f16 accumulate: D/C are 2 x .f16x2 registers.
#define MMA16816H(c0, c1, a0, a1, a2, a3, b0, b1) \
    asm volatile("mma.sync.aligned.m16n8k16.row.col.f16.f16.f16.f16 " \
                 "{%0,%1}, {%2,%3,%4,%5}, {%6,%7}, {%0,%1};" \
                 : "+r"(c0), "+r"(c1) \
                 : "r"(a0), "r"(a1), "r"(a2), "r"(a3), "r"(b0), "r"(b1))

// ---------------- gather + L2 normalize + align dot (+f16 store) -------------
// grid 1024 x block 256. Warp-per-row, one row per warp. Lane l owns dims
// [4l, 4l+4). int64-vs-int32 index detection per-warp (odd 32-bit lanes of an
// int64 array of values < 2^31 are all zero).
__global__ void __launch_bounds__(256) gather_norm_kernel(
        const void* __restrict__ u_raw, const void* __restrict__ v_raw,
        const float* __restrict__ emb) {
    const int lane = threadIdx.x & 31;
    const int warp = threadIdx.x >> 5;
    const int row  = blockIdx.x * 8 + warp;

    const int* u32 = (const int*)u_raw;
    int nz = u32[2 * lane + 1];
    #pragma unroll
    for (int off = 16; off; off >>= 1)
        nz |= __shfl_xor_sync(0xffffffffu, nz, off);
    const bool is64 = (nz == 0);

    long long ui, vi;
    if (is64) {
        ui = ((const long long*)u_raw)[row];
        vi = ((const long long*)v_raw)[row];
    } else {
        ui = ((const int*)u_raw)[row];
        vi = ((const int*)v_raw)[row];
    }

    float4 xu = ((const float4*)(emb + ui * DIM))[lane];
    float4 xv = ((const float4*)(emb + vi * DIM))[lane];

    float su2 = xu.x * xu.x + xu.y * xu.y + xu.z * xu.z + xu.w * xu.w;
    float sv2 = xv.x * xv.x + xv.y * xv.y + xv.z * xv.z + xv.w * xv.w;
    #pragma unroll
    for (int off = 16; off; off >>= 1) {
        su2 += __shfl_xor_sync(0xffffffffu, su2, off);
        sv2 += __shfl_xor_sync(0xffffffffu, sv2, off);
    }

    float ru = 1.0f / fmaxf(sqrtf(su2), 1e-12f);
    float rv = 1.0f / fmaxf(sqrtf(sv2), 1e-12f);
    float sux = xu.x * ru, suy = xu.y * ru, suz = xu.z * ru, suw = xu.w * ru;
    float svx = xv.x * rv, svy = xv.y * rv, svz = xv.z * rv, svw = xv.w * rv;

    __half2 u01 = __floats2half2_rn(sux, suy);
    __half2 u23 = __floats2half2_rn(suz, suw);
    __half2 v01 = __floats2half2_rn(svx, svy);
    __half2 v23 = __floats2half2_rn(svz, svw);
    *(uint2*)&g_src[row * DIM + lane * 4] =
        make_uint2(*(uint32_t*)&u01, *(uint32_t*)&u23);
    *(uint2*)&g_pos[row * DIM + lane * 4] =
        make_uint2(*(uint32_t*)&v01, *(uint32_t*)&v23);

    float dp = sux * svx + suy * svy + suz * svz + suw * svw;
    #pragma unroll
    for (int off = 16; off; off >>= 1)
        dp += __shfl_xor_sync(0xffffffffu, dp, off);
    if (lane == 0) g_dot[row] = dp;
}

// ---------------- fused HMMA-f16 Gram (symmetric half) + exp sums ------------
// grid (64, 2, 2): x = row-block bi, y = matrix, z = t-range half.
// Tournament: tiles (bi, (bi+t)%64) for t in z's half of [0,NT), NT=32(+1 bi<32).
// Epilogue in packed f16x2: f32 FFMA arg -> cvt f16x2 -> ex2.f16x2 -> HADD2.
#define SM_A  0
#define SM_B0 TILE_BYTES
#define SM_B1 (2 * TILE_BYTES)
#define SM_TOTAL (3 * TILE_BYTES)

__device__ __forceinline__ void load_tile(uint32_t sdst, const uint4* eg,
                                          int row0, int tid) {
    #pragma unroll
    for (int it = 0; it < 8; it++) {
        int idx = tid + it * 256;
        int r = idx >> 4, c = idx & 15;
        CP_ASYNC16(sdst + r * SSTRIDE + c * 16, eg + (row0 + r) * 16 + c);
    }
}

__global__ void __launch_bounds__(256, 2) lse_kernel() {
    extern __shared__ char smem[];
    const uint32_t sbase = smem_u32(smem);
    const int tid = threadIdx.x;
    const int lane = tid & 31;
    const int warp_m = (tid >> 5) >> 2;   // 0..1 -> 64 rows each
    const int warp_n = (tid >> 5) & 3;    // 0..3 -> 32 cols each
    const int m_base = warp_m * 64;
    const int n_base = warp_n * 32;
    const int bi = blockIdx.x;
    const int my = blockIdx.y;
    const int zz = blockIdx.z;
    const int NT = 32 + (bi < 32 ? 1 : 0);
    const int t0 = zz * 16;
    const int tEnd = zz == 0 ? 16 : NT;

    const __half* e = (my == 0) ? g_src : g_pos;
    const uint4* eg = (const uint4*)e;

    // prologue: A + B(t0) in group0, B(t0+1) in group1
    load_tile(sbase + SM_A, eg, bi * 128, tid);
    load_tile(sbase + SM_B0, eg, ((bi + t0) & 63) * 128, tid);
    CP_COMMIT();
    load_tile(sbase + SM_B1, eg, ((bi + t0 + 1) & 63) * 128, tid);
    CP_COMMIT();

    const int l15 = lane & 15;
    const uint32_t aAddr0 = sbase + SM_A +
        (uint32_t)(m_base + l15) * SSTRIDE + (uint32_t)(lane >> 4) * 16;
    const uint32_t bOff0 =
        (uint32_t)(n_base + (l15 & 7)) * SSTRIDE + (uint32_t)(l15 >> 3) * 16;

    uint32_t acc[4][4][2];                // f16x2 accumulators
    #pragma unroll
    for (int mt = 0; mt < 4; mt++)
        #pragma unroll
        for (int nt = 0; nt < 4; nt++) { acc[mt][nt][0] = 0u; acc[mt][nt][1] = 0u; }

    float rowsum[8];
    #pragma unroll
    for (int j = 0; j < 8; j++) rowsum[j] = 0.f;

    const float CEX = 2.0f * 1.4426950408889634f;   // exp(2d-2) = 2^(CEX*d - CEX)

    for (int t = t0; t < tEnd; t++) {
        if (t < tEnd - 1) { CP_WAIT1(); } else { CP_WAIT0(); }
        __syncthreads();

        const uint32_t bAddr0 = sbase + ((t & 1) ? SM_B1 : SM_B0) + bOff0;

        #pragma unroll
        for (int k = 0; k < 8; k++) {
            uint32_t b[4][2];
            #pragma unroll
            for (int nt = 0; nt < 4; nt++)
                LDMATRIX_X2(b[nt][0], b[nt][1],
                            bAddr0 + nt * (8 * SSTRIDE) + k * 32);
            #pragma unroll
            for (int mt = 0; mt < 4; mt++) {
                uint32_t a0, a1, a2, a3;
                LDMATRIX_X4(a0, a1, a2, a3,
                            aAddr0 + mt * (16 * SSTRIDE) + k * 32);
                #pragma unroll
                for (int nt = 0; nt < 4; nt++)
                    MMA16816H(acc[mt][nt][0], acc[mt][nt][1],
                              a0, a1, a2, a3, b[nt][0], b[nt][1]);
            }
        }

        __syncthreads();            // all warps done reading this B buffer
        if (t + 2 < tEnd) {
            load_tile(sbase + ((t & 1) ? SM_B1 : SM_B0), eg,
                      ((bi + t + 2) & 63) * 128, tid);
            CP_COMMIT();
        }

        // epilogue (packed f16x2): ev = 2^(CEX*d - CEX)
        uint32_t cs2[4];
        #pragma unroll
        for (int nt = 0; nt < 4; nt++) cs2[nt] = 0u;

        #pragma unroll
        for (int mt = 0; mt < 4; mt++) {
            uint32_t sr01 = 0u, sr23 = 0u;      // half2 row partials
            #pragma unroll
            for (int nt = 0; nt < 4; nt++) {
                float2 f01 = __half22float2(*(__half2*)&acc[mt][nt][0]); // row r  : cols c, c+1
                float2 f23 = __half22float2(*(__half2*)&acc[mt][nt][1]); // row r+8: cols c, c+1
                uint32_t h01 = ex2h2(packh2(fmaf(CEX, f01.y, -CEX),
                                            fmaf(CEX, f01.x, -CEX)));
                uint32_t h23 = ex2h2(packh2(fmaf(CEX, f23.y, -CEX),
                                            fmaf(CEX, f23.x, -CEX)));
                sr01 = hadd2u(sr01, h01);
                sr23 = hadd2u(sr23, h23);
                cs2[nt] = hadd2u(cs2[nt], hadd2u(h01, h23));
                acc[mt][nt][0] = 0u; acc[mt][nt][1] = 0u;
            }
            float2 fr01 = __half22float2(*(__half2*)&sr01);
            float2 fr23 = __half22float2(*(__half2*)&sr23);
            rowsum[mt * 2]     += fr01.x + fr01.y;
            rowsum[mt * 2 + 1] += fr23.x + fr23.y;
        }

        if (t != 0) {
            // col sums: xor-reduce half2 over the 8 row-groups, store f32
            #pragma unroll
            for (int nt = 0; nt < 4; nt++) {
                uint32_t c = cs2[nt];
                c = hadd2u(c, __shfl_xor_sync(0xffffffffu, c, 4));
                c = hadd2u(c, __shfl_xor_sync(0xffffffffu, c, 8));
                c = hadd2u(c, __shfl_xor_sync(0xffffffffu, c, 16));
                cs2[nt] = c;
            }
            if (lane < 4) {
                int bj = (bi + t) & 63;
                float2* dst = (float2*)&g_cross[
                    ((((my * 64 + bj) * 33 + t) * 2 + warp_m) * 128)
                    + n_base + lane * 2];
                #pragma unroll
                for (int nt = 0; nt < 4; nt++) {
                    float2 f = __half22float2(*(__half2*)&cs2[nt]);
                    dst[nt * 4] = f;
                }
            }
        }
    }

    // ---- own row sums: quad lanes share rows ----
    #pragma unroll
    for (int j = 0; j < 8; j++) {
        rowsum[j] += __shfl_xor_sync(0xffffffffu, rowsum[j], 1);
        rowsum[j] += __shfl_xor_sync(0xffffffffu, rowsum[j], 2);
    }

    float* red = (float*)smem;            // reuse A region
    __syncthreads();
    if ((lane & 3) == 0) {
        #pragma unroll
        for (int mt = 0; mt < 4; mt++) {
            int row = m_base + mt * 16 + (lane >> 2);
            red[warp_n * 128 + row]     = rowsum[mt * 2];
            red[warp_n * 128 + row + 8] = rowsum[mt * 2 + 1];
        }
    }
    __syncthreads();
    if (tid < 128) {
        float s = red[tid] + red[128 + tid] + red[256 + tid] + red[384 + tid];
        g_rowsum[((my * 2 + zz) * 64 + bi) * 128 + tid] = s;
    }
}

// ------- per-row combine + log + block partial + fenced last-block finalize --
__global__ void __launch_bounds__(1024) reduce_kernel(float* __restrict__ out) {
    const int bi = blockIdx.x;
    const int my = blockIdx.y;
    const int tid = threadIdx.x;         // 0..1023
    const int r = tid & 127;
    const int q = tid >> 7;              // segment 0..7

    const float* cr = &g_cross[(my * 64 + bi) * 33 * 2 * 128 + r];
    float s = 0.f;
    if (q == 0) {
        s += g_rowsum[((my * 2 + 0) * 64 + bi) * 128 + r];
        s += g_rowsum[((my * 2 + 1) * 64 + bi) * 128 + r];
        #pragma unroll
        for (int t = 1; t <= 4; t++)  s += cr[t * 256] + cr[t * 256 + 128];
    } else if (q < 7) {
        const int tb = q * 4;            // q=1 -> 5..8, ..., q=6 -> 25..28
        #pragma unroll
        for (int t = 1; t <= 4; t++)
            s += cr[(tb + t) * 256] + cr[(tb + t) * 256 + 128];
    } else {
        const int tMax = (bi >= 32) ? 32 : 31;
        for (int t = 29; t <= tMax; t++) s += cr[t * 256] + cr[t * 256 + 128];
    }

    __shared__ float sm2[1024];
    sm2[tid] = s;
    __syncthreads();
    if (q == 0) {
        float v = sm2[r];
        #pragma unroll
        for (int j = 1; j < 8; j++) v += sm2[r + 128 * j];
        sm2[r] = logf(v);
    }
    __syncthreads();
    for (int st = 64; st; st >>= 1) {
        if (tid < st) sm2[tid] += sm2[tid + st];
        __syncthreads();
    }
    if (tid == 0) g_lse_partial[my * 64 + bi] = sm2[0];

    if (my == 0) {
        sm2[tid] = (tid < 128) ? g_dot[bi * 128 + tid] : 0.f;
        __syncthreads();
        for (int st = 64; st; st >>= 1) {
            if (tid < st) sm2[tid] += sm2[tid + st];
            __syncthreads();
        }
        if (tid == 0) g_dotp[bi] = sm2[0];
    }

    // ---- last-of-128-blocks finalize (threadfence + counter election) ----
    __shared__ int slast;
    __syncthreads();
    if (tid == 0) {
        __threadfence();
        int old = atomicAdd(&g_count, 1);
        slast = ((old & 127) == 127) ? 1 : 0;
    }
    __syncthreads();
    if (slast) {
        __threadfence();
        if (tid < 128) {
            sm2[tid]       = g_lse_partial[tid];
            sm2[256 + tid] = (tid < 64) ? g_dotp[tid] : 0.f;
        }
        __syncthreads();
        for (int st = 64; st; st >>= 1) {
            if (tid < st) {
                sm2[tid]       += sm2[tid + st];
                sm2[256 + tid] += sm2[256 + tid + st];
            }
            __syncthreads();
        }
        if (tid == 0) {
            float lsum = sm2[0];                    // full 128-partial sum
            float asum = sm2[256];                  // full 64-partial sum
            float align_mean = asum / (float)NPTS;
            float align = 2.0f - 2.0f * align_mean;
            float unif  = lsum / (float)NPTS;
            out[0] = 4.0f * align + 2.0f * unif;
        }
    }
}

// ---------------- launch ------------------------------------------------------
extern "C" void kernel_launch(void* const* d_in, const int* in_sizes, int n_in,
                              void* d_out, int out_size) {
    const void*  u   = d_in[0];
    const void*  v   = d_in[1];
    const float* emb = (const float*)d_in[2];

    cudaFuncSetAttribute(lse_kernel,
                         cudaFuncAttributeMaxDynamicSharedMemorySize, SM_TOTAL);

    gather_norm_kernel<<<1024, 256>>>(u, v, emb);
    lse_kernel<<<dim3(64, 2, 2), 256, SM_TOTAL>>>();
    reduce_kernel<<<dim3(64, 2), 1024>>>((float*)d_out);
}

// round 14
// speedup vs baseline: 2.1427x; 1.0038x over previous
#include <cuda_runtime.h>
#include <cuda_fp16.h>
#include <cstdint>

#define NPTS 8192
#define DIM 128
#define SSTRIDE 272                   // f16 tile row stride bytes (136 halves)
#define TILE_BYTES (128 * SSTRIDE)    // 34816

// packed half2 constants: C = 2*log2(e) rounded to f16 = 2.884765625 (0x41C5)
#define SCALE2 0x41C541C5u            // ( C,  C)
#define BIAS2  0xC1C5C1C5u            // (-C, -C)

// ---------------- scratch (device globals; no allocations allowed) ----------
__device__ __half g_src[NPTS * DIM];
__device__ __half g_pos[NPTS * DIM];
__device__ float g_dot[NPTS];
__device__ float g_rowsum[2 * 2 * NPTS];            // [my][z][bi][row]
__device__ float g_cross[2 * 64 * 33 * 2 * 128];    // [my][bj][t][warp_m][row]
__device__ float g_lse_partial[128];                // [my(2)][row-block(64)]
__device__ float g_dotp[64];
__device__ int   g_count;                           // last-block election counter

// ---------------- PTX helpers ------------------------------------------------
__device__ __forceinline__ uint32_t smem_u32(const void* p) {
    uint32_t a;
    asm("{ .reg .u64 t; cvta.to.shared.u64 t, %1; cvt.u32.u64 %0, t; }"
        : "=r"(a) : "l"(p));
    return a;
}

__device__ __forceinline__ uint32_t ex2h2(uint32_t a) {
    uint32_t d;
    asm("ex2.approx.f16x2 %0, %1;" : "=r"(d) : "r"(a));
    return d;
}
__device__ __forceinline__ uint32_t hadd2u(uint32_t a, uint32_t b) {
    uint32_t d;
    asm("add.f16x2 %0, %1, %2;" : "=r"(d) : "r"(a), "r"(b));
    return d;
}
__device__ __forceinline__ uint32_t hmul2u(uint32_t a, uint32_t b) {
    uint32_t d;
    asm("mul.f16x2 %0, %1, %2;" : "=r"(d) : "r"(a), "r"(b));
    return d;
}

#define CP_ASYNC16(dst, src) \
    asm volatile("cp.async.cg.shared.global [%0], [%1], 16;" :: "r"(dst), "l"(src) : "memory")
#define CP_COMMIT() asm volatile("cp.async.commit_group;" ::: "memory")
#define CP_WAIT2()  asm volatile("cp.async.wait_group 2;" ::: "memory")
#define CP_WAIT1()  asm volatile("cp.async.wait_group 1;" ::: "memory")
#define CP_WAIT0()  asm volatile("cp.async.wait_group 0;" ::: "memory")

#define LDMATRIX_X4(r0, r1, r2, r3, addr) \
    asm volatile("ldmatrix.sync.aligned.m8n8.x4.shared.b16 {%0,%1,%2,%3}, [%4];" \
                 : "=r"(r0), "=r"(r1), "=r"(r2), "=r"(r3) : "r"(addr))
#define LDMATRIX_X2(r0, r1, addr) \
    asm volatile("ldmatrix.sync.aligned.m8n8.x2.shared.b16 {%0,%1}, [%2];" \
                 : "=r"(r0), "=r"(r1) : "r"(addr))

// f16 x f16 -> f16 accumulate: D/C are 2 x .f16x2 registers.
#define MMA16816H(c0, c1, a0, a1, a2, a3, b0, b1) \
    asm volatile("mma.sync.aligned.m16n8k16.row.col.f16.f16.f16.f16 " \
                 "{%0,%1}, {%2,%3,%4,%5}, {%6,%7}, {%0,%1};" \
                 : "+r"(c0), "+r"(c1) \
                 : "r"(a0), "r"(a1), "r"(a2), "r"(a3), "r"(b0), "r"(b1))

// ---------------- gather + L2 normalize + align dot (+f16 store) -------------
// grid 1024 x block 256. Warp-per-row. Lane l owns dims [4l, 4l+4).
// int64-vs-int32 index detection per-warp (odd 32-bit lanes of an int64 array
// of values < 2^31 are all zero).
__global__ void __launch_bounds__(256) gather_norm_kernel(
        const void* __restrict__ u_raw, const void* __restrict__ v_raw,
        const float* __restrict__ emb) {
    const int lane = threadIdx.x & 31;
    const int warp = threadIdx.x >> 5;
    const int row  = blockIdx.x * 8 + warp;

    const int* u32 = (const int*)u_raw;
    int nz = u32[2 * lane + 1];
    #pragma unroll
    for (int off = 16; off; off >>= 1)
        nz |= __shfl_xor_sync(0xffffffffu, nz, off);
    const bool is64 = (nz == 0);

    long long ui, vi;
    if (is64) {
        ui = ((const long long*)u_raw)[row];
        vi = ((const long long*)v_raw)[row];
    } else {
        ui = ((const int*)u_raw)[row];
        vi = ((const int*)v_raw)[row];
    }

    float4 xu = ((const float4*)(emb + ui * DIM))[lane];
    float4 xv = ((const float4*)(emb + vi * DIM))[lane];

    float su2 = xu.x * xu.x + xu.y * xu.y + xu.z * xu.z + xu.w * xu.w;
    float sv2 = xv.x * xv.x + xv.y * xv.y + xv.z * xv.z + xv.w * xv.w;
    #pragma unroll
    for (int off = 16; off; off >>= 1) {
        su2 += __shfl_xor_sync(0xffffffffu, su2, off);
        sv2 += __shfl_xor_sync(0xffffffffu, sv2, off);
    }

    float ru = 1.0f / fmaxf(sqrtf(su2), 1e-12f);
    float rv = 1.0f / fmaxf(sqrtf(sv2), 1e-12f);
    float sux = xu.x * ru, suy = xu.y * ru, suz = xu.z * ru, suw = xu.w * ru;
    float svx = xv.x * rv, svy = xv.y * rv, svz = xv.z * rv, svw = xv.w * rv;

    __half2 u01 = __floats2half2_rn(sux, suy);
    __half2 u23 = __floats2half2_rn(suz, suw);
    __half2 v01 = __floats2half2_rn(svx, svy);
    __half2 v23 = __floats2half2_rn(svz, svw);
    *(uint2*)&g_src[row * DIM + lane * 4] =
        make_uint2(*(uint32_t*)&u01, *(uint32_t*)&u23);
    *(uint2*)&g_pos[row * DIM + lane * 4] =
        make_uint2(*(uint32_t*)&v01, *(uint32_t*)&v23);

    float dp = sux * svx + suy * svy + suz * svz + suw * svw;
    #pragma unroll
    for (int off = 16; off; off >>= 1)
        dp += __shfl_xor_sync(0xffffffffu, dp, off);
    if (lane == 0) g_dot[row] = dp;
}

// ---------------- fused HMMA-f16 Gram (symmetric half) + exp sums ------------
// grid (64, 2, 2): x = row-block bi, y = matrix, z = t-range half.
// Tournament: tiles (bi, (bi+t)%64) for t in z's half of [0,NT), NT=32(+1 bi<32).
// A-tile pre-scaled by C in smem; acc initialized to -C -> acc = C*d - C and
// the epilogue is just ex2.f16x2 + HADD2.
#define SM_A  0
#define SM_B0 TILE_BYTES
#define SM_B1 (2 * TILE_BYTES)
#define SM_TOTAL (3 * TILE_BYTES)

__device__ __forceinline__ void load_tile(uint32_t sdst, const uint4* eg,
                                          int row0, int tid) {
    #pragma unroll
    for (int it = 0; it < 8; it++) {
        int idx = tid + it * 256;
        int r = idx >> 4, c = idx & 15;
        CP_ASYNC16(sdst + r * SSTRIDE + c * 16, eg + (row0 + r) * 16 + c);
    }
}

__global__ void __launch_bounds__(256, 2) lse_kernel() {
    extern __shared__ char smem[];
    const uint32_t sbase = smem_u32(smem);
    const int tid = threadIdx.x;
    const int lane = tid & 31;
    const int warp_m = (tid >> 5) >> 2;   // 0..1 -> 64 rows each
    const int warp_n = (tid >> 5) & 3;    // 0..3 -> 32 cols each
    const int m_base = warp_m * 64;
    const int n_base = warp_n * 32;
    const int bi = blockIdx.x;
    const int my = blockIdx.y;
    const int zz = blockIdx.z;
    const int NT = 32 + (bi < 32 ? 1 : 0);
    const int t0 = zz * 16;
    const int tEnd = zz == 0 ? 16 : NT;

    const __half* e = (my == 0) ? g_src : g_pos;
    const uint4* eg = (const uint4*)e;

    // prologue: A alone in group0, B(t0) group1, B(t0+1) group2
    load_tile(sbase + SM_A, eg, bi * 128, tid);
    CP_COMMIT();
    load_tile(sbase + SM_B0, eg, ((bi + t0) & 63) * 128, tid);
    CP_COMMIT();
    load_tile(sbase + SM_B1, eg, ((bi + t0 + 1) & 63) * 128, tid);
    CP_COMMIT();

    // A landed -> scale it by C in place (pad bytes scaled too: never read)
    CP_WAIT2();
    {
        uint32_t* aw = (uint32_t*)smem;
        #pragma unroll
        for (int i = tid; i < TILE_BYTES / 4; i += 256)
            aw[i] = hmul2u(aw[i], SCALE2);
    }

    const int l15 = lane & 15;
    const uint32_t aAddr0 = sbase + SM_A +
        (uint32_t)(m_base + l15) * SSTRIDE + (uint32_t)(lane >> 4) * 16;
    const uint32_t bOff0 =
        (uint32_t)(n_base + (l15 & 7)) * SSTRIDE + (uint32_t)(l15 >> 3) * 16;

    uint32_t acc[4][4][2];                // f16x2 accumulators, bias-initialized
    #pragma unroll
    for (int mt = 0; mt < 4; mt++)
        #pragma unroll
        for (int nt = 0; nt < 4; nt++) { acc[mt][nt][0] = BIAS2; acc[mt][nt][1] = BIAS2; }

    float rowsum[8];
    #pragma unroll
    for (int j = 0; j < 8; j++) rowsum[j] = 0.f;

    for (int t = t0; t < tEnd; t++) {
        if (t < tEnd - 1) { CP_WAIT1(); } else { CP_WAIT0(); }
        __syncthreads();                  // covers A-scale stores + B_t arrival

        const uint32_t bAddr0 = sbase + ((t & 1) ? SM_B1 : SM_B0) + bOff0;

        #pragma unroll
        for (int k = 0; k < 8; k++) {
            uint32_t b[4][2];
            #pragma unroll
            for (int nt = 0; nt < 4; nt++)
                LDMATRIX_X2(b[nt][0], b[nt][1],
                            bAddr0 + nt * (8 * SSTRIDE) + k * 32);
            #pragma unroll
            for (int mt = 0; mt < 4; mt++) {
                uint32_t a0, a1, a2, a3;
                LDMATRIX_X4(a0, a1, a2, a3,
                            aAddr0 + mt * (16 * SSTRIDE) + k * 32);
                #pragma unroll
                for (int nt = 0; nt < 4; nt++)
                    MMA16816H(acc[mt][nt][0], acc[mt][nt][1],
                              a0, a1, a2, a3, b[nt][0], b[nt][1]);
            }
        }

        __syncthreads();            // all warps done reading this B buffer
        if (t + 2 < tEnd) {
            load_tile(sbase + ((t & 1) ? SM_B1 : SM_B0), eg,
                      ((bi + t + 2) & 63) * 128, tid);
            CP_COMMIT();
        }

        // epilogue: acc already = C*d - C; ev = ex2(acc)
        uint32_t cs2[4];
        #pragma unroll
        for (int nt = 0; nt < 4; nt++) cs2[nt] = 0u;

        #pragma unroll
        for (int mt = 0; mt < 4; mt++) {
            uint32_t sr01 = 0u, sr23 = 0u;      // half2 row partials
            #pragma unroll
            for (int nt = 0; nt < 4; nt++) {
                uint32_t h01 = ex2h2(acc[mt][nt][0]);   // row r  : cols c,c+1
                uint32_t h23 = ex2h2(acc[mt][nt][1]);   // row r+8: cols c,c+1
                sr01 = hadd2u(sr01, h01);
                sr23 = hadd2u(sr23, h23);
                cs2[nt] = hadd2u(cs2[nt], hadd2u(h01, h23));
                acc[mt][nt][0] = BIAS2; acc[mt][nt][1] = BIAS2;
            }
            float2 fr01 = __half22float2(*(__half2*)&sr01);
            float2 fr23 = __half22float2(*(__half2*)&sr23);
            rowsum[mt * 2]     += fr01.x + fr01.y;
            rowsum[mt * 2 + 1] += fr23.x + fr23.y;
        }

        if (t != 0) {
            // col sums: xor-reduce half2 over the 8 row-groups, store f32
            #pragma unroll
            for (int nt = 0; nt < 4; nt++) {
                uint32_t c = cs2[nt];
                c = hadd2u(c, __shfl_xor_sync(0xffffffffu, c, 4));
                c = hadd2u(c, __shfl_xor_sync(0xffffffffu, c, 8));
                c = hadd2u(c, __shfl_xor_sync(0xffffffffu, c, 16));
                cs2[nt] = c;
            }
            if (lane < 4) {
                int bj = (bi + t) & 63;
                float2* dst = (float2*)&g_cross[
                    ((((my * 64 + bj) * 33 + t) * 2 + warp_m) * 128)
                    + n_base + lane * 2];
                #pragma unroll
                for (int nt = 0; nt < 4; nt++) {
                    float2 f = __half22float2(*(__half2*)&cs2[nt]);
                    dst[nt * 4] = f;
                }
            }
        }
    }

    // ---- own row sums: quad lanes share rows ----
    #pragma unroll
    for (int j = 0; j < 8; j++) {
        rowsum[j] += __shfl_xor_sync(0xffffffffu, rowsum[j], 1);
        rowsum[j] += __shfl_xor_sync(0xffffffffu, rowsum[j], 2);
    }

    float* red = (float*)smem;            // reuse A region
    __syncthreads();
    if ((lane & 3) == 0) {
        #pragma unroll
        for (int mt = 0; mt < 4; mt++) {
            int row = m_base + mt * 16 + (lane >> 2);
            red[warp_n * 128 + row]     = rowsum[mt * 2];
            red[warp_n * 128 + row + 8] = rowsum[mt * 2 + 1];
        }
    }
    __syncthreads();
    if (tid < 128) {
        float s = red[tid] + red[128 + tid] + red[256 + tid] + red[384 + tid];
        g_rowsum[((my * 2 + zz) * 64 + bi) * 128 + tid] = s;
    }
}

// ------- per-row combine + log + block partial + fenced last-block finalize --
__global__ void __launch_bounds__(1024) reduce_kernel(float* __restrict__ out) {
    const int bi = blockIdx.x;
    const int my = blockIdx.y;
    const int tid = threadIdx.x;         // 0..1023
    const int r = tid & 127;
    const int q = tid >> 7;              // segment 0..7

    const float* cr = &g_cross[(my * 64 + bi) * 33 * 2 * 128 + r];
    float s = 0.f;
    if (q == 0) {
        s += g_rowsum[((my * 2 + 0) * 64 + bi) * 128 + r];
        s += g_rowsum[((my * 2 + 1) * 64 + bi) * 128 + r];
        #pragma unroll
        for (int t = 1; t <= 4; t++)  s += cr[t * 256] + cr[t * 256 + 128];
    } else if (q < 7) {
        const int tb = q * 4;            // q=1 -> 5..8, ..., q=6 -> 25..28
        #pragma unroll
        for (int t = 1; t <= 4; t++)
            s += cr[(tb + t) * 256] + cr[(tb + t) * 256 + 128];
    } else {
        const int tMax = (bi >= 32) ? 32 : 31;
        for (int t = 29; t <= tMax; t++) s += cr[t * 256] + cr[t * 256 + 128];
    }

    __shared__ float sm2[1024];
    sm2[tid] = s;
    __syncthreads();
    if (q == 0) {
        float v = sm2[r];
        #pragma unroll
        for (int j = 1; j < 8; j++) v += sm2[r + 128 * j];
        sm2[r] = logf(v);
    }
    __syncthreads();
    for (int st = 64; st; st >>= 1) {
        if (tid < st) sm2[tid] += sm2[tid + st];
        __syncthreads();
    }
    if (tid == 0) g_lse_partial[my * 64 + bi] = sm2[0];

    if (my == 0) {
        sm2[tid] = (tid < 128) ? g_dot[bi * 128 + tid] : 0.f;
        __syncthreads();
        for (int st = 64; st; st >>= 1) {
            if (tid < st) sm2[tid] += sm2[tid + st];
            __syncthreads();
        }
        if (tid == 0) g_dotp[bi] = sm2[0];
    }

    // ---- last-of-128-blocks finalize (threadfence + counter election) ----
    __shared__ int slast;
    __syncthreads();
    if (tid == 0) {
        __threadfence();
        int old = atomicAdd(&g_count, 1);
        slast = ((old & 127) == 127) ? 1 : 0;
    }
    __syncthreads();
    if (slast) {
        __threadfence();
        if (tid < 128) {
            sm2[tid]       = g_lse_partial[tid];
            sm2[256 + tid] = (tid < 64) ? g_dotp[tid] : 0.f;
        }
        __syncthreads();
        for (int st = 64; st; st >>= 1) {
            if (tid < st) {
                sm2[tid]       += sm2[tid + st];
                sm2[256 + tid] += sm2[256 + tid + st];
            }
            __syncthreads();
        }
        if (tid == 0) {
            float lsum = sm2[0];                    // full 128-partial sum
            float asum = sm2[256];                  // full 64-partial sum
            float align_mean = asum / (float)NPTS;
            float align = 2.0f - 2.0f * align_mean;
            float unif  = lsum / (float)NPTS;
            out[0] = 4.0f * align + 2.0f * unif;
        }
    }
}

// ---------------- launch ------------------------------------------------------
extern "C" void kernel_launch(void* const* d_in, const int* in_sizes, int n_in,
                              void* d_out, int out_size) {
    const void*  u   = d_in[0];
    const void*  v   = d_in[1];
    const float* emb = (const float*)d_in[2];

    cudaFuncSetAttribute(lse_kernel,
                         cudaFuncAttributeMaxDynamicSharedMemorySize, SM_TOTAL);

    gather_norm_kernel<<<1024, 256>>>(u, v, emb);
    lse_kernel<<<dim3(64, 2, 2), 256, SM_TOTAL>>>();
    reduce_kernel<<<dim3(64, 2), 1024>>>((float*)d_out);
}